// round 7
// baseline (speedup 1.0000x reference)
#include <cuda_runtime.h>

#define NQ 10
#define NL 4
#define NC 4
#define BATCH 2048

typedef unsigned long long u64;

// ============================================================================
// GF(2) linear-map tracking of the CNOT ring (all compile-time).
// Index bits: wire q <-> bit (9-q). Bits 5..9 = lane bits 0..4, bits 0..4 = local.
// Invariant: psi_phys[p] = sigma[F p], F = T^l at layer l.
// Gate on physical bit b: stored pair-XOR mask = column b of T^l,
//                         role(s) = <row_b(T^{-l}), s>.
// Measurement sign mask for bit b: row b of T^{-NL}.
// ============================================================================

struct G10 { unsigned r[10]; };

__host__ __device__ constexpr G10 gid10() {
    G10 c{};
    for (int i = 0; i < 10; i++) c.r[i] = 1u << i;
    return c;
}
__host__ __device__ constexpr G10 gmul(const G10 a, const G10 b) {
    G10 c{};
    for (int i = 0; i < 10; i++) {
        unsigned m = 0;
        for (int j = 0; j < 10; j++)
            if ((a.r[i] >> j) & 1u) m ^= b.r[j];
        c.r[i] = m;
    }
    return c;
}
__host__ __device__ constexpr G10 makeT() {
    G10 c{};
    for (int i = 0; i < 8; i++) c.r[i] = (1u << i) | (1u << (i + 1));
    c.r[8] = 0x301u;
    c.r[9] = 0x201u;
    return c;
}
__host__ __device__ constexpr G10 makeTinv() {
    G10 c{};
    for (int i = 0; i < 9; i++) c.r[i] = (0x3FFu >> i) << i;
    c.r[9] = 0x1FFu;
    return c;
}
__host__ __device__ constexpr G10 gpow(const G10 a, int k) {
    G10 c = gid10();
    for (int t = 0; t < k; t++) c = gmul(a, c);
    return c;
}
__host__ __device__ constexpr bool iseq(const G10 a, const G10 b) {
    for (int i = 0; i < 10; i++) if (a.r[i] != b.r[i]) return false;
    return true;
}
static_assert(iseq(gmul(makeT(), makeTinv()), gid10()), "Tinv wrong");

__host__ __device__ constexpr unsigned colmask(const G10 m, int b) {
    unsigned v = 0;
    for (int i = 0; i < 10; i++) v |= ((m.r[i] >> b) & 1u) << i;
    return v;
}
__host__ __device__ constexpr unsigned gate_mask(int l, int q) {
    return colmask(gpow(makeT(), l), 9 - q);
}
__host__ __device__ constexpr unsigned gate_role(int l, int q) {
    return gpow(makeTinv(), l).r[9 - q];
}
__host__ __device__ constexpr unsigned meas_row(int wire) {
    return gpow(makeTinv(), NL).r[9 - wire];
}
__host__ __device__ constexpr int par10(unsigned v) {
    int p = 0;
    for (int i = 0; i < 10; i++) p ^= (int)((v >> i) & 1u);
    return p;
}

// ============================================================================
// Packed f32x2 helpers (Blackwell FFMA2)
// ============================================================================
__device__ __forceinline__ u64 pk(float lo, float hi) {
    u64 d;
    asm("mov.b64 %0, {%1, %2};" : "=l"(d) : "f"(lo), "f"(hi));
    return d;
}
__device__ __forceinline__ void upk(u64 v, float& lo, float& hi) {
    asm("mov.b64 {%0, %1}, %2;" : "=f"(lo), "=f"(hi) : "l"(v));
}
__device__ __forceinline__ u64 f2fma(u64 a, u64 b, u64 c) {
    u64 d;
    asm("fma.rn.f32x2 %0, %1, %2, %3;" : "=l"(d) : "l"(a), "l"(b), "l"(c));
    return d;
}
__device__ __forceinline__ u64 f2fma_neg(u64 a, u64 b, u64 c) {
    // c - a*b
    u64 m, d;
    asm("mul.rn.f32x2 %0, %1, %2;" : "=l"(m) : "l"(a), "l"(b));
    asm("sub.rn.f32x2 %0, %1, %2;" : "=l"(d) : "l"(c), "l"(m));
    return d;
}
__device__ __forceinline__ u64 f2mul(u64 a, u64 b) {
    u64 d;
    asm("mul.rn.f32x2 %0, %1, %2;" : "=l"(d) : "l"(a), "l"(b));
    return d;
}
__device__ __forceinline__ u64 swap2(u64 v) { return (v >> 32) | (v << 32); }
__device__ __forceinline__ u64 shfl64(u64 v, int m) {
    return __shfl_xor_sync(0xffffffffu, v, m);
}

// ============================================================================
// Rot matrix precompute: [NL][NQ][8]
// ============================================================================
__device__ float g_rot[NL * NQ * 8];

__global__ void rot_precompute_kernel(const float* __restrict__ w) {
    int i = threadIdx.x;
    if (i < NL * NQ) {
        float phi = w[i * 3 + 0], theta = w[i * 3 + 1], omega = w[i * 3 + 2];
        float st, ct;  sincosf(0.5f * theta, &st, &ct);
        float spo, cpo; sincosf(0.5f * (phi + omega), &spo, &cpo);
        float spm, cpm; sincosf(0.5f * (phi - omega), &spm, &cpm);
        float* m = g_rot + i * 8;
        m[0] =  cpo * ct;  m[1] = -spo * ct;
        m[2] = -cpm * st;  m[3] = -spm * st;
        m[4] =  cpm * st;  m[5] = -spm * st;
        m[6] =  cpo * ct;  m[7] =  spo * ct;
    }
}

// Fused gate column {m00, m01} of M = Rot * RX (SU(2): m11=conj(m00), m10=-conj(m01))
__device__ __forceinline__ void build_fused_AB(const float* __restrict__ rm,
                                               float c, float s,
                                               float& Ar, float& Ai,
                                               float& Br, float& Bi) {
    Ar =  c * rm[0] + s * rm[3];   // m00r
    Ai =  c * rm[1] - s * rm[2];   // m00i
    Br =  s * rm[1] + c * rm[2];   // m01r
    Bi = -s * rm[0] + c * rm[3];   // m01i
}

// Column 0 only (acting on |0>): a = M00, b = M10.
__device__ __forceinline__ void fused_col0(const float* __restrict__ rm,
                                           float c, float s,
                                           float& ar_, float& ai_,
                                           float& br_, float& bi_) {
    ar_ = c * rm[0] + s * rm[3];
    ai_ = c * rm[1] - s * rm[2];
    br_ = c * rm[4] + s * rm[7];
    bi_ = c * rm[5] - s * rm[6];
}

// ============================================================================
// Generalized 1q SU(2) gate, sign-unified roles.
// out_r = Ar*sr - sAi*si + sBr*or - Bi*oi
// out_i = Ar*si + sAi*sr + sBr*oi + Bi*or
// where sAi = sigma*Ai, sBr = sigma*Br, sigma = role sign = (-1)^(rl ^ par(j&RJ))
// ============================================================================
template <int LM, int JM, int RL, int RJ>
__device__ __forceinline__ void gate_apply(u64* Vr, u64* Vi, int lane,
                                           float Ar, float Ai, float Br, float Bi) {
    constexpr int JH = JM >> 1, JL = JM & 1;
    constexpr int JHB = JH & (-JH);
    constexpr int RJH = RJ >> 1, RJL = RJ & 1;

    const bool rl = (RL != 0) && ((__popc(lane & RL) & 1) != 0);
    const float aAi = rl ? -Ai : Ai;   // sigma for constexpr-parity-0 slots
    const float aBr = rl ? -Br : Br;

    // Uniform packs
    const u64 PAr  = pk(Ar, Ar);
    const u64 PBi  = pk(Bi, Bi);
    const u64 PBiN = pk(-Bi, -Bi);
    // Role-signed packs; variant v = par(g & RJH); hi slot flips if RJL
    const u64 PsAi0  = pk(aAi, RJL ? -aAi : aAi);
    const u64 PsAiN0 = pk(-aAi, RJL ? aAi : -aAi);
    const u64 PsBr0  = pk(aBr, RJL ? -aBr : aBr);
    u64 PsAi1 = PsAi0, PsAiN1 = PsAiN0, PsBr1 = PsBr0;
    if (RJH != 0) {
        PsAi1  = pk(-aAi, RJL ? aAi : -aAi);
        PsAiN1 = pk(aAi, RJL ? -aAi : aAi);
        PsBr1  = pk(-aBr, RJL ? aBr : -aBr);
    }

#pragma unroll
    for (int g = 0; g < 16; g++) {
        if (JH != 0 && (g & JHB) != 0) continue;  // one rep per {g, g^JH} orbit
        const int pg = g ^ JH;
        const u64 sr = Vr[g], si = Vi[g];
        u64 or_g, oi_g;
        u64 sr2 = 0, si2 = 0, or_p = 0, oi_p = 0;
        if (LM != 0) { or_g = shfl64(Vr[pg], LM); oi_g = shfl64(Vi[pg], LM); }
        else         { or_g = Vr[pg];             oi_g = Vi[pg]; }
        if (JH != 0) {
            sr2 = Vr[pg]; si2 = Vi[pg];
            if (LM != 0) { or_p = shfl64(Vr[g], LM); oi_p = shfl64(Vi[g], LM); }
            else         { or_p = sr;                oi_p = si; }
        }
        if (JL != 0) {
            or_g = swap2(or_g); oi_g = swap2(oi_g);
            if (JH != 0) { or_p = swap2(or_p); oi_p = swap2(oi_p); }
        }
        {
            const bool v = (__popc(g & RJH) & 1) != 0;
            const u64 pAi = v ? PsAi1 : PsAi0, pAiN = v ? PsAiN1 : PsAiN0;
            const u64 pBr = v ? PsBr1 : PsBr0;
            Vr[g] = f2fma(PAr, sr, f2fma(pAiN, si, f2fma(pBr, or_g, f2mul(PBiN, oi_g))));
            Vi[g] = f2fma(PAr, si, f2fma(pAi,  sr, f2fma(pBr, oi_g, f2mul(PBi,  or_g))));
        }
        if (JH != 0) {
            const bool v = (__popc(pg & RJH) & 1) != 0;
            const u64 pAi = v ? PsAi1 : PsAi0, pAiN = v ? PsAiN1 : PsAiN0;
            const u64 pBr = v ? PsBr1 : PsBr0;
            Vr[pg] = f2fma(PAr, sr2, f2fma(pAiN, si2, f2fma(pBr, or_p, f2mul(PBiN, oi_p))));
            Vi[pg] = f2fma(PAr, si2, f2fma(pAi,  sr2, f2fma(pBr, oi_p, f2mul(PBi,  or_p))));
        }
    }
}

__global__ void __launch_bounds__(64, 7)
vqc_kernel(const float* __restrict__ x,
           const float* __restrict__ bias,
           const float* __restrict__ scale,
           float* __restrict__ out) {
    __shared__ float srot[NL * NQ * 8];
    for (int i = threadIdx.x; i < NL * NQ * 8; i += blockDim.x)
        srot[i] = g_rot[i];
    __syncthreads();

    const int lane = threadIdx.x & 31;
    const int b = (blockIdx.x * blockDim.x + threadIdx.x) >> 5;

    float xc = 0.0f, xs = 0.0f;
    if (lane < NQ) {
        float h = 0.5f * x[b * NQ + lane];
        sincosf(h, &xs, &xc);
    }

    // ========================================================================
    // Layer 0 via product-state construction.
    // ========================================================================
    u64 Vr[16], Vi[16];

    // Lane factor: wires 0..4 <-> lane bits 4..0
    float Lfr = 1.0f, Lfi = 0.0f;
#pragma unroll
    for (int q = 0; q < 5; q++) {
        float c_ = __shfl_sync(0xffffffffu, xc, q);
        float s_ = __shfl_sync(0xffffffffu, xs, q);
        float ar_, ai_, br_, bi_;
        fused_col0(srot + q * 8, c_, s_, ar_, ai_, br_, bi_);
        const bool bit = ((lane >> (4 - q)) & 1) != 0;
        const float fr = bit ? br_ : ar_;
        const float fi = bit ? bi_ : ai_;
        const float nr = Lfr * fr - Lfi * fi;
        const float ni = Lfr * fi + Lfi * fr;
        Lfr = nr; Lfi = ni;
    }

    // Local wires 5..9 <-> local bits 4..0 (wire q -> local bit 9-m)
    float lar[5], lai[5], lbr[5], lbi[5];
#pragma unroll
    for (int m = 0; m < 5; m++) {
        const int q = 9 - m;
        float c_ = __shfl_sync(0xffffffffu, xc, q);
        float s_ = __shfl_sync(0xffffffffu, xs, q);
        fused_col0(srot + q * 8, c_, s_, lar[m], lai[m], lbr[m], lbi[m]);
    }

    {
        const float e0r = Lfr * lar[0] - Lfi * lai[0];
        const float e0i = Lfr * lai[0] + Lfi * lar[0];
        const float e1r = Lfr * lbr[0] - Lfi * lbi[0];
        const float e1i = Lfr * lbi[0] + Lfi * lbr[0];
        Vr[0] = pk(e0r, e1r);
        Vi[0] = pk(e0i, e1i);
    }
#pragma unroll
    for (int m = 1; m < 5; m++) {
        const u64 Ar2 = pk(lar[m], lar[m]), Ai2 = pk(lai[m], lai[m]);
        const u64 Br2 = pk(lbr[m], lbr[m]), Bi2 = pk(lbi[m], lbi[m]);
        const int half = 1 << (m - 1);
#pragma unroll
        for (int g = 0; g < 16; g++) {
            if (g >= half) continue;
            const u64 r = Vr[g], i = Vi[g];
            Vr[g | half] = f2fma_neg(i, Bi2, f2mul(r, Br2));
            Vi[g | half] = f2fma(r, Bi2, f2mul(i, Br2));
            Vr[g]        = f2fma_neg(i, Ai2, f2mul(r, Ar2));
            Vi[g]        = f2fma(r, Ai2, f2mul(i, Ar2));
        }
    }

#define APPLY_GATE(L, Q)                                                        \
    do {                                                                        \
        float c_ = __shfl_sync(0xffffffffu, xc, Q);                             \
        float s_ = __shfl_sync(0xffffffffu, xs, Q);                             \
        float Ar_, Ai_, Br_, Bi_;                                               \
        build_fused_AB(srot + ((L) * NQ + (Q)) * 8, c_, s_, Ar_, Ai_, Br_, Bi_);\
        constexpr unsigned gm_ = gate_mask(L, Q);                               \
        constexpr unsigned gr_ = gate_role(L, Q);                               \
        gate_apply<(int)((gm_ >> 5) & 31u), (int)(gm_ & 31u),                   \
                   (int)((gr_ >> 5) & 31u), (int)(gr_ & 31u)>(                  \
            Vr, Vi, lane, Ar_, Ai_, Br_, Bi_);                                  \
    } while (0)

#define APPLY_LAYER(L)                                                          \
    APPLY_GATE(L, 0); APPLY_GATE(L, 1); APPLY_GATE(L, 2); APPLY_GATE(L, 3);     \
    APPLY_GATE(L, 4); APPLY_GATE(L, 5); APPLY_GATE(L, 6); APPLY_GATE(L, 7);     \
    APPLY_GATE(L, 8); APPLY_GATE(L, 9);

    APPLY_LAYER(1)
    APPLY_LAYER(2)
    APPLY_LAYER(3)

#undef APPLY_LAYER
#undef APPLY_GATE

    // Single-pass measurement: 4 signed sums over probabilities.
    constexpr unsigned rows0 = meas_row(0), rows1 = meas_row(1);
    constexpr unsigned rows2 = meas_row(2), rows3 = meas_row(3);
    float S0 = 0.f, S1 = 0.f, S2 = 0.f, S3 = 0.f;
#pragma unroll
    for (int g = 0; g < 16; g++) {
        u64 P = f2fma(Vr[g], Vr[g], f2mul(Vi[g], Vi[g]));
        float plo, phi_;
        upk(P, plo, phi_);
#pragma unroll
        for (int h = 0; h < 2; h++) {
            const int j = 2 * g + h;
            const float pv = h ? phi_ : plo;
            S0 += par10(j & (rows0 & 31u)) ? -pv : pv;
            S1 += par10(j & (rows1 & 31u)) ? -pv : pv;
            S2 += par10(j & (rows2 & 31u)) ? -pv : pv;
            S3 += par10(j & (rows3 & 31u)) ? -pv : pv;
        }
    }
    float ev[NC];
    {
        const unsigned lrow[NC] = {rows0 >> 5, rows1 >> 5, rows2 >> 5, rows3 >> 5};
        float Ss[NC] = {S0, S1, S2, S3};
#pragma unroll
        for (int c = 0; c < NC; c++) {
            const bool ls = (__popc(lane & (int)lrow[c]) & 1) != 0;
            float v = ls ? -Ss[c] : Ss[c];
            v += __shfl_xor_sync(0xffffffffu, v, 16);
            v += __shfl_xor_sync(0xffffffffu, v, 8);
            v += __shfl_xor_sync(0xffffffffu, v, 4);
            v += __shfl_xor_sync(0xffffffffu, v, 2);
            v += __shfl_xor_sync(0xffffffffu, v, 1);
            ev[c] = v;
        }
    }

    if (lane == 0) {
        float t0 = (ev[0] + bias[0]) * scale[0];
        float t1 = (ev[1] + bias[1]) * scale[1];
        float t2 = (ev[2] + bias[2]) * scale[2];
        float t3 = (ev[3] + bias[3]) * scale[3];
        float m = fmaxf(fmaxf(t0, t1), fmaxf(t2, t3));
        float e0 = expf(t0 - m), e1 = expf(t1 - m), e2 = expf(t2 - m), e3 = expf(t3 - m);
        float inv = 1.0f / (e0 + e1 + e2 + e3);
        reinterpret_cast<float4*>(out)[b] =
            make_float4(e0 * inv, e1 * inv, e2 * inv, e3 * inv);
    }
}

extern "C" void kernel_launch(void* const* d_in, const int* in_sizes, int n_in,
                              void* d_out, int out_size) {
    const float* x       = (const float*)d_in[0];  // (B, NQ)
    const float* weights = (const float*)d_in[1];  // (NL, NQ, 3)
    const float* bias    = (const float*)d_in[2];  // (C,)
    const float* scale   = (const float*)d_in[3];  // (C,)
    float* out = (float*)d_out;                    // (B, C)

    rot_precompute_kernel<<<1, 64>>>(weights);
    // 2 warps per block -> 2 batch elements per block; balanced placement
    vqc_kernel<<<BATCH / 2, 64>>>(x, bias, scale, out);
}

// round 8
// speedup vs baseline: 1.0717x; 1.0717x over previous
#include <cuda_runtime.h>

#define NQ 10
#define NL 4
#define NC 4
#define BATCH 2048

typedef unsigned long long u64;

// ============================================================================
// GF(2) linear-map tracking of the CNOT ring (all compile-time).
// Index bits: wire q <-> bit (9-q). Bits 5..9 = lane bits 0..4, bits 0..4 = local.
// Invariant: psi_phys[p] = sigma[F p], F = T^l at layer l.
// Gate on physical bit b: stored pair-XOR mask = column b of T^l,
//                         role(s) = <row_b(T^{-l}), s>.
// Measurement sign mask for bit b: row b of T^{-NL}.
// ============================================================================

struct G10 { unsigned r[10]; };

__host__ __device__ constexpr G10 gid10() {
    G10 c{};
    for (int i = 0; i < 10; i++) c.r[i] = 1u << i;
    return c;
}
__host__ __device__ constexpr G10 gmul(const G10 a, const G10 b) {
    G10 c{};
    for (int i = 0; i < 10; i++) {
        unsigned m = 0;
        for (int j = 0; j < 10; j++)
            if ((a.r[i] >> j) & 1u) m ^= b.r[j];
        c.r[i] = m;
    }
    return c;
}
__host__ __device__ constexpr G10 makeT() {
    G10 c{};
    for (int i = 0; i < 8; i++) c.r[i] = (1u << i) | (1u << (i + 1));
    c.r[8] = 0x301u;
    c.r[9] = 0x201u;
    return c;
}
__host__ __device__ constexpr G10 makeTinv() {
    G10 c{};
    for (int i = 0; i < 9; i++) c.r[i] = (0x3FFu >> i) << i;
    c.r[9] = 0x1FFu;
    return c;
}
__host__ __device__ constexpr G10 gpow(const G10 a, int k) {
    G10 c = gid10();
    for (int t = 0; t < k; t++) c = gmul(a, c);
    return c;
}
__host__ __device__ constexpr bool iseq(const G10 a, const G10 b) {
    for (int i = 0; i < 10; i++) if (a.r[i] != b.r[i]) return false;
    return true;
}
static_assert(iseq(gmul(makeT(), makeTinv()), gid10()), "Tinv wrong");

__host__ __device__ constexpr unsigned colmask(const G10 m, int b) {
    unsigned v = 0;
    for (int i = 0; i < 10; i++) v |= ((m.r[i] >> b) & 1u) << i;
    return v;
}
__host__ __device__ constexpr unsigned gate_mask(int l, int q) {
    return colmask(gpow(makeT(), l), 9 - q);
}
__host__ __device__ constexpr unsigned gate_role(int l, int q) {
    return gpow(makeTinv(), l).r[9 - q];
}
__host__ __device__ constexpr unsigned meas_row(int wire) {
    return gpow(makeTinv(), NL).r[9 - wire];
}
__host__ __device__ constexpr int par10(unsigned v) {
    int p = 0;
    for (int i = 0; i < 10; i++) p ^= (int)((v >> i) & 1u);
    return p;
}

// ============================================================================
// Packed f32x2 helpers (Blackwell FFMA2)
// ============================================================================
__device__ __forceinline__ u64 pk(float lo, float hi) {
    u64 d;
    asm("mov.b64 %0, {%1, %2};" : "=l"(d) : "f"(lo), "f"(hi));
    return d;
}
__device__ __forceinline__ void upk(u64 v, float& lo, float& hi) {
    asm("mov.b64 {%0, %1}, %2;" : "=f"(lo), "=f"(hi) : "l"(v));
}
__device__ __forceinline__ u64 f2fma(u64 a, u64 b, u64 c) {
    u64 d;
    asm("fma.rn.f32x2 %0, %1, %2, %3;" : "=l"(d) : "l"(a), "l"(b), "l"(c));
    return d;
}
__device__ __forceinline__ u64 f2fma_neg(u64 a, u64 b, u64 c) {
    // c - a*b
    u64 m, d;
    asm("mul.rn.f32x2 %0, %1, %2;" : "=l"(m) : "l"(a), "l"(b));
    asm("sub.rn.f32x2 %0, %1, %2;" : "=l"(d) : "l"(c), "l"(m));
    return d;
}
__device__ __forceinline__ u64 f2mul(u64 a, u64 b) {
    u64 d;
    asm("mul.rn.f32x2 %0, %1, %2;" : "=l"(d) : "l"(a), "l"(b));
    return d;
}
__device__ __forceinline__ u64 swap2(u64 v) { return (v >> 32) | (v << 32); }
__device__ __forceinline__ u64 shfl64(u64 v, int m) {
    return __shfl_xor_sync(0xffffffffu, v, m);
}

// ============================================================================
// Rot matrix precompute: [NL][NQ][8]
// ============================================================================
__device__ float g_rot[NL * NQ * 8];

__global__ void rot_precompute_kernel(const float* __restrict__ w) {
    int i = threadIdx.x;
    if (i < NL * NQ) {
        float phi = w[i * 3 + 0], theta = w[i * 3 + 1], omega = w[i * 3 + 2];
        float st, ct;  sincosf(0.5f * theta, &st, &ct);
        float spo, cpo; sincosf(0.5f * (phi + omega), &spo, &cpo);
        float spm, cpm; sincosf(0.5f * (phi - omega), &spm, &cpm);
        float* m = g_rot + i * 8;
        m[0] =  cpo * ct;  m[1] = -spo * ct;
        m[2] = -cpm * st;  m[3] = -spm * st;
        m[4] =  cpm * st;  m[5] = -spm * st;
        m[6] =  cpo * ct;  m[7] =  spo * ct;
    }
}

// Fused gate column {m00, m01} of M = Rot * RX (SU(2): m11=conj(m00), m10=-conj(m01))
__device__ __forceinline__ void build_fused_AB(const float* __restrict__ rm,
                                               float c, float s,
                                               float& Ar, float& Ai,
                                               float& Br, float& Bi) {
    Ar =  c * rm[0] + s * rm[3];   // m00r
    Ai =  c * rm[1] - s * rm[2];   // m00i
    Br =  s * rm[1] + c * rm[2];   // m01r
    Bi = -s * rm[0] + c * rm[3];   // m01i
}

// Column 0 only (acting on |0>): a = M00, b = M10.
__device__ __forceinline__ void fused_col0(const float* __restrict__ rm,
                                           float c, float s,
                                           float& ar_, float& ai_,
                                           float& br_, float& bi_) {
    ar_ = c * rm[0] + s * rm[3];
    ai_ = c * rm[1] - s * rm[2];
    br_ = c * rm[4] + s * rm[7];
    bi_ = c * rm[5] - s * rm[6];
}

// ============================================================================
// Generalized 1q SU(2) gate, sign-unified roles.
// out_r = Ar*sr - sAi*si + sBr*or - Bi*oi
// out_i = Ar*si + sAi*sr + sBr*oi + Bi*or
// where sAi = sigma*Ai, sBr = sigma*Br, sigma = role sign = (-1)^(rl ^ par(j&RJ))
// ============================================================================
template <int LM, int JM, int RL, int RJ>
__device__ __forceinline__ void gate_apply(u64* Vr, u64* Vi, int lane,
                                           float Ar, float Ai, float Br, float Bi) {
    constexpr int JH = JM >> 1, JL = JM & 1;
    constexpr int JHB = JH & (-JH);
    constexpr int RJH = RJ >> 1, RJL = RJ & 1;

    const bool rl = (RL != 0) && ((__popc(lane & RL) & 1) != 0);
    const float aAi = rl ? -Ai : Ai;   // sigma for constexpr-parity-0 slots
    const float aBr = rl ? -Br : Br;

    // Uniform packs
    const u64 PAr  = pk(Ar, Ar);
    const u64 PBi  = pk(Bi, Bi);
    const u64 PBiN = pk(-Bi, -Bi);
    // Role-signed packs; variant v = par(g & RJH); hi slot flips if RJL
    const u64 PsAi0  = pk(aAi, RJL ? -aAi : aAi);
    const u64 PsAiN0 = pk(-aAi, RJL ? aAi : -aAi);
    const u64 PsBr0  = pk(aBr, RJL ? -aBr : aBr);
    u64 PsAi1 = PsAi0, PsAiN1 = PsAiN0, PsBr1 = PsBr0;
    if (RJH != 0) {
        PsAi1  = pk(-aAi, RJL ? aAi : -aAi);
        PsAiN1 = pk(aAi, RJL ? -aAi : aAi);
        PsBr1  = pk(-aBr, RJL ? aBr : -aBr);
    }

#pragma unroll
    for (int g = 0; g < 16; g++) {
        if (JH != 0 && (g & JHB) != 0) continue;  // one rep per {g, g^JH} orbit
        const int pg = g ^ JH;
        const u64 sr = Vr[g], si = Vi[g];
        u64 or_g, oi_g;
        u64 sr2 = 0, si2 = 0, or_p = 0, oi_p = 0;
        if (LM != 0) { or_g = shfl64(Vr[pg], LM); oi_g = shfl64(Vi[pg], LM); }
        else         { or_g = Vr[pg];             oi_g = Vi[pg]; }
        if (JH != 0) {
            sr2 = Vr[pg]; si2 = Vi[pg];
            if (LM != 0) { or_p = shfl64(Vr[g], LM); oi_p = shfl64(Vi[g], LM); }
            else         { or_p = sr;                oi_p = si; }
        }
        if (JL != 0) {
            or_g = swap2(or_g); oi_g = swap2(oi_g);
            if (JH != 0) { or_p = swap2(or_p); oi_p = swap2(oi_p); }
        }
        {
            const bool v = (__popc(g & RJH) & 1) != 0;
            const u64 pAi = v ? PsAi1 : PsAi0, pAiN = v ? PsAiN1 : PsAiN0;
            const u64 pBr = v ? PsBr1 : PsBr0;
            Vr[g] = f2fma(PAr, sr, f2fma(pAiN, si, f2fma(pBr, or_g, f2mul(PBiN, oi_g))));
            Vi[g] = f2fma(PAr, si, f2fma(pAi,  sr, f2fma(pBr, oi_g, f2mul(PBi,  or_g))));
        }
        if (JH != 0) {
            const bool v = (__popc(pg & RJH) & 1) != 0;
            const u64 pAi = v ? PsAi1 : PsAi0, pAiN = v ? PsAiN1 : PsAiN0;
            const u64 pBr = v ? PsBr1 : PsBr0;
            Vr[pg] = f2fma(PAr, sr2, f2fma(pAiN, si2, f2fma(pBr, or_p, f2mul(PBiN, oi_p))));
            Vi[pg] = f2fma(PAr, si2, f2fma(pAi,  sr2, f2fma(pBr, oi_p, f2mul(PBi,  or_p))));
        }
    }
}

__global__ void __launch_bounds__(256, 2)
vqc_kernel(const float* __restrict__ x,
           const float* __restrict__ bias,
           const float* __restrict__ scale,
           float* __restrict__ out) {
    __shared__ float srot[NL * NQ * 8];
    for (int i = threadIdx.x; i < NL * NQ * 8; i += blockDim.x)
        srot[i] = g_rot[i];
    __syncthreads();

    const int lane = threadIdx.x & 31;
    const int b = (blockIdx.x * blockDim.x + threadIdx.x) >> 5;

    float xc = 0.0f, xs = 0.0f;
    if (lane < NQ) {
        float h = 0.5f * x[b * NQ + lane];
        sincosf(h, &xs, &xc);
    }

    // ========================================================================
    // Layer 0 via product-state construction.
    // ========================================================================
    u64 Vr[16], Vi[16];

    // Lane factor: wires 0..4 <-> lane bits 4..0
    float Lfr = 1.0f, Lfi = 0.0f;
#pragma unroll
    for (int q = 0; q < 5; q++) {
        float c_ = __shfl_sync(0xffffffffu, xc, q);
        float s_ = __shfl_sync(0xffffffffu, xs, q);
        float ar_, ai_, br_, bi_;
        fused_col0(srot + q * 8, c_, s_, ar_, ai_, br_, bi_);
        const bool bit = ((lane >> (4 - q)) & 1) != 0;
        const float fr = bit ? br_ : ar_;
        const float fi = bit ? bi_ : ai_;
        const float nr = Lfr * fr - Lfi * fi;
        const float ni = Lfr * fi + Lfi * fr;
        Lfr = nr; Lfi = ni;
    }

    // Local wires 5..9 <-> local bits 4..0 (wire q -> local bit 9-q)
    float lar[5], lai[5], lbr[5], lbi[5];
#pragma unroll
    for (int m = 0; m < 5; m++) {
        const int q = 9 - m;
        float c_ = __shfl_sync(0xffffffffu, xc, q);
        float s_ = __shfl_sync(0xffffffffu, xs, q);
        fused_col0(srot + q * 8, c_, s_, lar[m], lai[m], lbr[m], lbi[m]);
    }

    {
        const float e0r = Lfr * lar[0] - Lfi * lai[0];
        const float e0i = Lfr * lai[0] + Lfi * lar[0];
        const float e1r = Lfr * lbr[0] - Lfi * lbi[0];
        const float e1i = Lfr * lbi[0] + Lfi * lbr[0];
        Vr[0] = pk(e0r, e1r);
        Vi[0] = pk(e0i, e1i);
    }
#pragma unroll
    for (int m = 1; m < 5; m++) {
        const u64 Ar2 = pk(lar[m], lar[m]), Ai2 = pk(lai[m], lai[m]);
        const u64 Br2 = pk(lbr[m], lbr[m]), Bi2 = pk(lbi[m], lbi[m]);
        const int half = 1 << (m - 1);
#pragma unroll
        for (int g = 0; g < 16; g++) {
            if (g >= half) continue;
            const u64 r = Vr[g], i = Vi[g];
            Vr[g | half] = f2fma_neg(i, Bi2, f2mul(r, Br2));
            Vi[g | half] = f2fma(r, Bi2, f2mul(i, Br2));
            Vr[g]        = f2fma_neg(i, Ai2, f2mul(r, Ar2));
            Vi[g]        = f2fma(r, Ai2, f2mul(i, Ar2));
        }
    }

#define APPLY_GATE(L, Q)                                                        \
    do {                                                                        \
        float c_ = __shfl_sync(0xffffffffu, xc, Q);                             \
        float s_ = __shfl_sync(0xffffffffu, xs, Q);                             \
        float Ar_, Ai_, Br_, Bi_;                                               \
        build_fused_AB(srot + ((L) * NQ + (Q)) * 8, c_, s_, Ar_, Ai_, Br_, Bi_);\
        constexpr unsigned gm_ = gate_mask(L, Q);                               \
        constexpr unsigned gr_ = gate_role(L, Q);                               \
        gate_apply<(int)((gm_ >> 5) & 31u), (int)(gm_ & 31u),                   \
                   (int)((gr_ >> 5) & 31u), (int)(gr_ & 31u)>(                  \
            Vr, Vi, lane, Ar_, Ai_, Br_, Bi_);                                  \
    } while (0)

#define APPLY_LAYER(L)                                                          \
    APPLY_GATE(L, 0); APPLY_GATE(L, 1); APPLY_GATE(L, 2); APPLY_GATE(L, 3);     \
    APPLY_GATE(L, 4); APPLY_GATE(L, 5); APPLY_GATE(L, 6); APPLY_GATE(L, 7);     \
    APPLY_GATE(L, 8); APPLY_GATE(L, 9);

    APPLY_LAYER(1)
    APPLY_LAYER(2)
    APPLY_LAYER(3)

#undef APPLY_LAYER
#undef APPLY_GATE

    // Single-pass measurement: 4 signed sums over probabilities.
    constexpr unsigned rows0 = meas_row(0), rows1 = meas_row(1);
    constexpr unsigned rows2 = meas_row(2), rows3 = meas_row(3);
    float S0 = 0.f, S1 = 0.f, S2 = 0.f, S3 = 0.f;
#pragma unroll
    for (int g = 0; g < 16; g++) {
        u64 P = f2fma(Vr[g], Vr[g], f2mul(Vi[g], Vi[g]));
        float plo, phi_;
        upk(P, plo, phi_);
#pragma unroll
        for (int h = 0; h < 2; h++) {
            const int j = 2 * g + h;
            const float pv = h ? phi_ : plo;
            S0 += par10(j & (rows0 & 31u)) ? -pv : pv;
            S1 += par10(j & (rows1 & 31u)) ? -pv : pv;
            S2 += par10(j & (rows2 & 31u)) ? -pv : pv;
            S3 += par10(j & (rows3 & 31u)) ? -pv : pv;
        }
    }
    float ev[NC];
    {
        const unsigned lrow[NC] = {rows0 >> 5, rows1 >> 5, rows2 >> 5, rows3 >> 5};
        float Ss[NC] = {S0, S1, S2, S3};
#pragma unroll
        for (int c = 0; c < NC; c++) {
            const bool ls = (__popc(lane & (int)lrow[c]) & 1) != 0;
            float v = ls ? -Ss[c] : Ss[c];
            v += __shfl_xor_sync(0xffffffffu, v, 16);
            v += __shfl_xor_sync(0xffffffffu, v, 8);
            v += __shfl_xor_sync(0xffffffffu, v, 4);
            v += __shfl_xor_sync(0xffffffffu, v, 2);
            v += __shfl_xor_sync(0xffffffffu, v, 1);
            ev[c] = v;
        }
    }

    if (lane == 0) {
        float t0 = (ev[0] + bias[0]) * scale[0];
        float t1 = (ev[1] + bias[1]) * scale[1];
        float t2 = (ev[2] + bias[2]) * scale[2];
        float t3 = (ev[3] + bias[3]) * scale[3];
        float m = fmaxf(fmaxf(t0, t1), fmaxf(t2, t3));
        float e0 = expf(t0 - m), e1 = expf(t1 - m), e2 = expf(t2 - m), e3 = expf(t3 - m);
        float inv = 1.0f / (e0 + e1 + e2 + e3);
        reinterpret_cast<float4*>(out)[b] =
            make_float4(e0 * inv, e1 * inv, e2 * inv, e3 * inv);
    }
}

extern "C" void kernel_launch(void* const* d_in, const int* in_sizes, int n_in,
                              void* d_out, int out_size) {
    const float* x       = (const float*)d_in[0];  // (B, NQ)
    const float* weights = (const float*)d_in[1];  // (NL, NQ, 3)
    const float* bias    = (const float*)d_in[2];  // (C,)
    const float* scale   = (const float*)d_in[3];  // (C,)
    float* out = (float*)d_out;                    // (B, C)

    rot_precompute_kernel<<<1, 64>>>(weights);
    // 8 warps per block (all 4 SMSPs fed), 2 blocks resident per SM
    vqc_kernel<<<BATCH / 8, 256>>>(x, bias, scale, out);
}

// round 10
// speedup vs baseline: 1.1099x; 1.0356x over previous
#include <cuda_runtime.h>

#define NQ 10
#define NL 4
#define NC 4
#define BATCH 2048

typedef unsigned long long u64;

// ============================================================================
// GF(2) linear-map tracking of the CNOT ring (all compile-time).
// Index bits: wire q <-> bit (9-q). Bits 5..9 = lane bits 0..4, bits 0..4 = local.
// Invariant: psi_phys[p] = sigma[F p], F = T^l at layer l.
// Gate on physical bit b: stored pair-XOR mask = column b of T^l,
//                         role(s) = <row_b(T^{-l}), s>.
// Measurement sign mask for bit b: row b of T^{-NL}.
// Layer-3 gates are gauged by D = diag(w, conj(w)): legal because
// (T^{-3} T^3) = I makes all layer-3 D's commute to the end, where diagonal
// phases drop out of probabilities.
// ============================================================================

struct G10 { unsigned r[10]; };

__host__ __device__ constexpr G10 gid10() {
    G10 c{};
    for (int i = 0; i < 10; i++) c.r[i] = 1u << i;
    return c;
}
__host__ __device__ constexpr G10 gmul(const G10 a, const G10 b) {
    G10 c{};
    for (int i = 0; i < 10; i++) {
        unsigned m = 0;
        for (int j = 0; j < 10; j++)
            if ((a.r[i] >> j) & 1u) m ^= b.r[j];
        c.r[i] = m;
    }
    return c;
}
__host__ __device__ constexpr G10 makeT() {
    G10 c{};
    for (int i = 0; i < 8; i++) c.r[i] = (1u << i) | (1u << (i + 1));
    c.r[8] = 0x301u;
    c.r[9] = 0x201u;
    return c;
}
__host__ __device__ constexpr G10 makeTinv() {
    G10 c{};
    for (int i = 0; i < 9; i++) c.r[i] = (0x3FFu >> i) << i;
    c.r[9] = 0x1FFu;
    return c;
}
__host__ __device__ constexpr G10 gpow(const G10 a, int k) {
    G10 c = gid10();
    for (int t = 0; t < k; t++) c = gmul(a, c);
    return c;
}
__host__ __device__ constexpr bool iseq(const G10 a, const G10 b) {
    for (int i = 0; i < 10; i++) if (a.r[i] != b.r[i]) return false;
    return true;
}
static_assert(iseq(gmul(makeT(), makeTinv()), gid10()), "Tinv wrong");

__host__ __device__ constexpr unsigned colmask(const G10 m, int b) {
    unsigned v = 0;
    for (int i = 0; i < 10; i++) v |= ((m.r[i] >> b) & 1u) << i;
    return v;
}
__host__ __device__ constexpr unsigned gate_mask(int l, int q) {
    return colmask(gpow(makeT(), l), 9 - q);
}
__host__ __device__ constexpr unsigned gate_role(int l, int q) {
    return gpow(makeTinv(), l).r[9 - q];
}
__host__ __device__ constexpr unsigned meas_row(int wire) {
    return gpow(makeTinv(), NL).r[9 - wire];
}
__host__ __device__ constexpr int par10(unsigned v) {
    int p = 0;
    for (int i = 0; i < 10; i++) p ^= (int)((v >> i) & 1u);
    return p;
}

// ============================================================================
// Packed f32x2 helpers (Blackwell FFMA2)
// ============================================================================
__device__ __forceinline__ u64 pk(float lo, float hi) {
    u64 d;
    asm("mov.b64 %0, {%1, %2};" : "=l"(d) : "f"(lo), "f"(hi));
    return d;
}
__device__ __forceinline__ void upk(u64 v, float& lo, float& hi) {
    asm("mov.b64 {%0, %1}, %2;" : "=f"(lo), "=f"(hi) : "l"(v));
}
__device__ __forceinline__ u64 f2fma(u64 a, u64 b, u64 c) {
    u64 d;
    asm("fma.rn.f32x2 %0, %1, %2, %3;" : "=l"(d) : "l"(a), "l"(b), "l"(c));
    return d;
}
__device__ __forceinline__ u64 f2fma_neg(u64 a, u64 b, u64 c) {
    // c - a*b
    u64 m, d;
    asm("mul.rn.f32x2 %0, %1, %2;" : "=l"(m) : "l"(a), "l"(b));
    asm("sub.rn.f32x2 %0, %1, %2;" : "=l"(d) : "l"(c), "l"(m));
    return d;
}
__device__ __forceinline__ u64 f2mul(u64 a, u64 b) {
    u64 d;
    asm("mul.rn.f32x2 %0, %1, %2;" : "=l"(d) : "l"(a), "l"(b));
    return d;
}
__device__ __forceinline__ u64 swap2(u64 v) { return (v >> 32) | (v << 32); }
__device__ __forceinline__ u64 shfl64(u64 v, int m) {
    return __shfl_xor_sync(0xffffffffu, v, m);
}

// ============================================================================
// Rot matrix precompute: [NL][NQ][8]
// ============================================================================
__device__ float g_rot[NL * NQ * 8];

__global__ void rot_precompute_kernel(const float* __restrict__ w) {
    int i = threadIdx.x;
    if (i < NL * NQ) {
        float phi = w[i * 3 + 0], theta = w[i * 3 + 1], omega = w[i * 3 + 2];
        float st, ct;  sincosf(0.5f * theta, &st, &ct);
        float spo, cpo; sincosf(0.5f * (phi + omega), &spo, &cpo);
        float spm, cpm; sincosf(0.5f * (phi - omega), &spm, &cpm);
        float* m = g_rot + i * 8;
        m[0] =  cpo * ct;  m[1] = -spo * ct;
        m[2] = -cpm * st;  m[3] = -spm * st;
        m[4] =  cpm * st;  m[5] = -spm * st;
        m[6] =  cpo * ct;  m[7] =  spo * ct;
    }
}

// Fused gate column {m00, m01} of M = Rot * RX (SU(2): m11=conj(m00), m10=-conj(m01))
__device__ __forceinline__ void build_fused_AB(const float* __restrict__ rm,
                                               float c, float s,
                                               float& Ar, float& Ai,
                                               float& Br, float& Bi) {
    Ar =  c * rm[0] + s * rm[3];   // m00r
    Ai =  c * rm[1] - s * rm[2];   // m00i
    Br =  s * rm[1] + c * rm[2];   // m01r
    Bi = -s * rm[0] + c * rm[3];   // m01i
}

// Gauged fused gate for the FINAL layer only: D*M with D = diag(w, conj(w)),
// w = conj(m00)/|m00|.  Result: diag real A = |m00|, off-diag B' = w*m01,
// role1 = (-conj(B'), A).  Legal only when D commutes to the measurement.
__device__ __forceinline__ void build_fused_gauged(const float* __restrict__ rm,
                                                   float c, float s,
                                                   float& Ar, float& Br, float& Bi) {
    const float A0r =  c * rm[0] + s * rm[3];
    const float A0i =  c * rm[1] - s * rm[2];
    const float B0r =  s * rm[1] + c * rm[2];
    const float B0i = -s * rm[0] + c * rm[3];
    const float n2  = A0r * A0r + A0i * A0i;
    const float inv = rsqrtf(n2 + 1e-30f);
    const float wr  =  A0r * inv;
    const float wi  = -A0i * inv;
    Ar = n2 * inv;
    Br = wr * B0r - wi * B0i;
    Bi = wr * B0i + wi * B0r;
}

// Column 0 only (acting on |0>): a = M00, b = M10.
__device__ __forceinline__ void fused_col0(const float* __restrict__ rm,
                                           float c, float s,
                                           float& ar_, float& ai_,
                                           float& br_, float& bi_) {
    ar_ = c * rm[0] + s * rm[3];
    ai_ = c * rm[1] - s * rm[2];
    br_ = c * rm[4] + s * rm[7];
    bi_ = c * rm[5] - s * rm[6];
}

// ============================================================================
// Generalized 1q SU(2) gate, sign-unified roles (8 packed ops / group):
// out_r = Ar*sr - sAi*si + sBr*or - Bi*oi
// out_i = Ar*si + sAi*sr + sBr*oi + Bi*or
// sAi = sigma*Ai, sBr = sigma*Br, sigma = (-1)^(par(lane&RL) ^ par(j&RJ))
// ============================================================================
template <int LM, int JM, int RL, int RJ>
__device__ __forceinline__ void gate_apply(u64* Vr, u64* Vi, int lane,
                                           float Ar, float Ai, float Br, float Bi) {
    constexpr int JH = JM >> 1, JL = JM & 1;
    constexpr int JHB = JH & (-JH);
    constexpr int RJH = RJ >> 1, RJL = RJ & 1;

    const bool rl = (RL != 0) && ((__popc(lane & RL) & 1) != 0);
    const float aAi = rl ? -Ai : Ai;
    const float aBr = rl ? -Br : Br;

    const u64 PAr  = pk(Ar, Ar);
    const u64 PBi  = pk(Bi, Bi);
    const u64 PBiN = pk(-Bi, -Bi);
    const u64 PsAi0  = pk(aAi, RJL ? -aAi : aAi);
    const u64 PsAiN0 = pk(-aAi, RJL ? aAi : -aAi);
    const u64 PsBr0  = pk(aBr, RJL ? -aBr : aBr);
    u64 PsAi1 = PsAi0, PsAiN1 = PsAiN0, PsBr1 = PsBr0;
    if (RJH != 0) {
        PsAi1  = pk(-aAi, RJL ? aAi : -aAi);
        PsAiN1 = pk(aAi, RJL ? -aAi : aAi);
        PsBr1  = pk(-aBr, RJL ? aBr : -aBr);
    }

#pragma unroll
    for (int g = 0; g < 16; g++) {
        if (JH != 0 && (g & JHB) != 0) continue;  // one rep per {g, g^JH} orbit
        const int pg = g ^ JH;
        const u64 sr = Vr[g], si = Vi[g];
        u64 or_g, oi_g;
        u64 sr2 = 0, si2 = 0, or_p = 0, oi_p = 0;
        if (LM != 0) { or_g = shfl64(Vr[pg], LM); oi_g = shfl64(Vi[pg], LM); }
        else         { or_g = Vr[pg];             oi_g = Vi[pg]; }
        if (JH != 0) {
            sr2 = Vr[pg]; si2 = Vi[pg];
            if (LM != 0) { or_p = shfl64(Vr[g], LM); oi_p = shfl64(Vi[g], LM); }
            else         { or_p = sr;                oi_p = si; }
        }
        if (JL != 0) {
            or_g = swap2(or_g); oi_g = swap2(oi_g);
            if (JH != 0) { or_p = swap2(or_p); oi_p = swap2(oi_p); }
        }
        {
            const bool v = (__popc(g & RJH) & 1) != 0;
            const u64 pAi = v ? PsAi1 : PsAi0, pAiN = v ? PsAiN1 : PsAiN0;
            const u64 pBr = v ? PsBr1 : PsBr0;
            Vr[g] = f2fma(PAr, sr, f2fma(pAiN, si, f2fma(pBr, or_g, f2mul(PBiN, oi_g))));
            Vi[g] = f2fma(PAr, si, f2fma(pAi,  sr, f2fma(pBr, oi_g, f2mul(PBi,  or_g))));
        }
        if (JH != 0) {
            const bool v = (__popc(pg & RJH) & 1) != 0;
            const u64 pAi = v ? PsAi1 : PsAi0, pAiN = v ? PsAiN1 : PsAiN0;
            const u64 pBr = v ? PsBr1 : PsBr0;
            Vr[pg] = f2fma(PAr, sr2, f2fma(pAiN, si2, f2fma(pBr, or_p, f2mul(PBiN, oi_p))));
            Vi[pg] = f2fma(PAr, si2, f2fma(pAi,  sr2, f2fma(pBr, oi_p, f2mul(PBi,  or_p))));
        }
    }
}

// ============================================================================
// Gauged gate (A real) for the final layer — 6 packed ops / group:
// role0: out = A*s + B*o ; role1: out = A*s - conj(B)*o
// out_r = A*sr + sBr*or - Bi*oi ; out_i = A*si + sBr*oi + Bi*or
// ============================================================================
template <int LM, int JM, int RL, int RJ>
__device__ __forceinline__ void gate_apply_gauged(u64* Vr, u64* Vi, int lane,
                                                  float Ar, float Br, float Bi) {
    constexpr int JH = JM >> 1, JL = JM & 1;
    constexpr int JHB = JH & (-JH);
    constexpr int RJH = RJ >> 1, RJL = RJ & 1;

    const bool rl = (RL != 0) && ((__popc(lane & RL) & 1) != 0);
    const float aBr = rl ? -Br : Br;

    const u64 PAr  = pk(Ar, Ar);
    const u64 PBi  = pk(Bi, Bi);
    const u64 PBiN = pk(-Bi, -Bi);
    const u64 PsBr0 = pk(aBr, RJL ? -aBr : aBr);
    u64 PsBr1 = PsBr0;
    if (RJH != 0) PsBr1 = pk(-aBr, RJL ? aBr : -aBr);

#pragma unroll
    for (int g = 0; g < 16; g++) {
        if (JH != 0 && (g & JHB) != 0) continue;
        const int pg = g ^ JH;
        const u64 sr = Vr[g], si = Vi[g];
        u64 or_g, oi_g;
        u64 sr2 = 0, si2 = 0, or_p = 0, oi_p = 0;
        if (LM != 0) { or_g = shfl64(Vr[pg], LM); oi_g = shfl64(Vi[pg], LM); }
        else         { or_g = Vr[pg];             oi_g = Vi[pg]; }
        if (JH != 0) {
            sr2 = Vr[pg]; si2 = Vi[pg];
            if (LM != 0) { or_p = shfl64(Vr[g], LM); oi_p = shfl64(Vi[g], LM); }
            else         { or_p = sr;                oi_p = si; }
        }
        if (JL != 0) {
            or_g = swap2(or_g); oi_g = swap2(oi_g);
            if (JH != 0) { or_p = swap2(or_p); oi_p = swap2(oi_p); }
        }
        {
            const bool v = (__popc(g & RJH) & 1) != 0;
            const u64 pBr = v ? PsBr1 : PsBr0;
            Vr[g] = f2fma(PAr, sr, f2fma(pBr, or_g, f2mul(PBiN, oi_g)));
            Vi[g] = f2fma(PAr, si, f2fma(pBr, oi_g, f2mul(PBi,  or_g)));
        }
        if (JH != 0) {
            const bool v = (__popc(pg & RJH) & 1) != 0;
            const u64 pBr = v ? PsBr1 : PsBr0;
            Vr[pg] = f2fma(PAr, sr2, f2fma(pBr, or_p, f2mul(PBiN, oi_p)));
            Vi[pg] = f2fma(PAr, si2, f2fma(pBr, oi_p, f2mul(PBi,  or_p)));
        }
    }
}

__global__ void __launch_bounds__(256, 2)
vqc_kernel(const float* __restrict__ x,
           const float* __restrict__ bias,
           const float* __restrict__ scale,
           float* __restrict__ out) {
    __shared__ float srot[NL * NQ * 8];
    for (int i = threadIdx.x; i < NL * NQ * 8; i += blockDim.x)
        srot[i] = g_rot[i];
    __syncthreads();

    const int lane = threadIdx.x & 31;
    const int b = (blockIdx.x * blockDim.x + threadIdx.x) >> 5;

    float xc = 0.0f, xs = 0.0f;
    if (lane < NQ) {
        float h = 0.5f * x[b * NQ + lane];
        sincosf(h, &xs, &xc);
    }

    // ========================================================================
    // Layer 0 via product-state construction.
    // ========================================================================
    u64 Vr[16], Vi[16];

    // Lane factor: wires 0..4 <-> lane bits 4..0
    float Lfr = 1.0f, Lfi = 0.0f;
#pragma unroll
    for (int q = 0; q < 5; q++) {
        float c_ = __shfl_sync(0xffffffffu, xc, q);
        float s_ = __shfl_sync(0xffffffffu, xs, q);
        float ar_, ai_, br_, bi_;
        fused_col0(srot + q * 8, c_, s_, ar_, ai_, br_, bi_);
        const bool bit = ((lane >> (4 - q)) & 1) != 0;
        const float fr = bit ? br_ : ar_;
        const float fi = bit ? bi_ : ai_;
        const float nr = Lfr * fr - Lfi * fi;
        const float ni = Lfr * fi + Lfi * fr;
        Lfr = nr; Lfi = ni;
    }

    // Local wires 5..9 <-> local bits 4..0 (wire q -> local bit 9-q)
    float lar[5], lai[5], lbr[5], lbi[5];
#pragma unroll
    for (int m = 0; m < 5; m++) {
        const int q = 9 - m;
        float c_ = __shfl_sync(0xffffffffu, xc, q);
        float s_ = __shfl_sync(0xffffffffu, xs, q);
        fused_col0(srot + q * 8, c_, s_, lar[m], lai[m], lbr[m], lbi[m]);
    }

    {
        const float e0r = Lfr * lar[0] - Lfi * lai[0];
        const float e0i = Lfr * lai[0] + Lfi * lar[0];
        const float e1r = Lfr * lbr[0] - Lfi * lbi[0];
        const float e1i = Lfr * lbi[0] + Lfi * lbr[0];
        Vr[0] = pk(e0r, e1r);
        Vi[0] = pk(e0i, e1i);
    }
#pragma unroll
    for (int m = 1; m < 5; m++) {
        const u64 Ar2 = pk(lar[m], lar[m]), Ai2 = pk(lai[m], lai[m]);
        const u64 Br2 = pk(lbr[m], lbr[m]), Bi2 = pk(lbi[m], lbi[m]);
        const int half = 1 << (m - 1);
#pragma unroll
        for (int g = 0; g < 16; g++) {
            if (g >= half) continue;
            const u64 r = Vr[g], i = Vi[g];
            Vr[g | half] = f2fma_neg(i, Bi2, f2mul(r, Br2));
            Vi[g | half] = f2fma(r, Bi2, f2mul(i, Br2));
            Vr[g]        = f2fma_neg(i, Ai2, f2mul(r, Ar2));
            Vi[g]        = f2fma(r, Ai2, f2mul(i, Ar2));
        }
    }

#define APPLY_GATE(L, Q)                                                        \
    do {                                                                        \
        float c_ = __shfl_sync(0xffffffffu, xc, Q);                             \
        float s_ = __shfl_sync(0xffffffffu, xs, Q);                             \
        float Ar_, Ai_, Br_, Bi_;                                               \
        build_fused_AB(srot + ((L) * NQ + (Q)) * 8, c_, s_, Ar_, Ai_, Br_, Bi_);\
        constexpr unsigned gm_ = gate_mask(L, Q);                               \
        constexpr unsigned gr_ = gate_role(L, Q);                               \
        gate_apply<(int)((gm_ >> 5) & 31u), (int)(gm_ & 31u),                   \
                   (int)((gr_ >> 5) & 31u), (int)(gr_ & 31u)>(                  \
            Vr, Vi, lane, Ar_, Ai_, Br_, Bi_);                                  \
    } while (0)

#define APPLY_GATE_GAUGED(L, Q)                                                 \
    do {                                                                        \
        float c_ = __shfl_sync(0xffffffffu, xc, Q);                             \
        float s_ = __shfl_sync(0xffffffffu, xs, Q);                             \
        float Ar_, Br_, Bi_;                                                    \
        build_fused_gauged(srot + ((L) * NQ + (Q)) * 8, c_, s_, Ar_, Br_, Bi_); \
        constexpr unsigned gm_ = gate_mask(L, Q);                               \
        constexpr unsigned gr_ = gate_role(L, Q);                               \
        gate_apply_gauged<(int)((gm_ >> 5) & 31u), (int)(gm_ & 31u),            \
                          (int)((gr_ >> 5) & 31u), (int)(gr_ & 31u)>(           \
            Vr, Vi, lane, Ar_, Br_, Bi_);                                       \
    } while (0)

#define APPLY_LAYER(L)                                                          \
    APPLY_GATE(L, 0); APPLY_GATE(L, 1); APPLY_GATE(L, 2); APPLY_GATE(L, 3);     \
    APPLY_GATE(L, 4); APPLY_GATE(L, 5); APPLY_GATE(L, 6); APPLY_GATE(L, 7);     \
    APPLY_GATE(L, 8); APPLY_GATE(L, 9);

    APPLY_LAYER(1)
    APPLY_LAYER(2)

    // Final layer: gauged gates (D = diag(w, w~) commutes to measurement
    // because (T^{-3} T^3) = I; diagonal phases are unobservable there).
    APPLY_GATE_GAUGED(3, 0); APPLY_GATE_GAUGED(3, 1);
    APPLY_GATE_GAUGED(3, 2); APPLY_GATE_GAUGED(3, 3);
    APPLY_GATE_GAUGED(3, 4); APPLY_GATE_GAUGED(3, 5);
    APPLY_GATE_GAUGED(3, 6); APPLY_GATE_GAUGED(3, 7);
    APPLY_GATE_GAUGED(3, 8); APPLY_GATE_GAUGED(3, 9);

#undef APPLY_LAYER
#undef APPLY_GATE
#undef APPLY_GATE_GAUGED

    // Single-pass measurement: 4 signed sums over probabilities.
    constexpr unsigned rows0 = meas_row(0), rows1 = meas_row(1);
    constexpr unsigned rows2 = meas_row(2), rows3 = meas_row(3);
    float S0 = 0.f, S1 = 0.f, S2 = 0.f, S3 = 0.f;
#pragma unroll
    for (int g = 0; g < 16; g++) {
        u64 P = f2fma(Vr[g], Vr[g], f2mul(Vi[g], Vi[g]));
        float plo, phi_;
        upk(P, plo, phi_);
#pragma unroll
        for (int h = 0; h < 2; h++) {
            const int j = 2 * g + h;
            const float pv = h ? phi_ : plo;
            S0 += par10(j & (rows0 & 31u)) ? -pv : pv;
            S1 += par10(j & (rows1 & 31u)) ? -pv : pv;
            S2 += par10(j & (rows2 & 31u)) ? -pv : pv;
            S3 += par10(j & (rows3 & 31u)) ? -pv : pv;
        }
    }
    float ev[NC];
    {
        const unsigned lrow[NC] = {rows0 >> 5, rows1 >> 5, rows2 >> 5, rows3 >> 5};
        float Ss[NC] = {S0, S1, S2, S3};
#pragma unroll
        for (int c = 0; c < NC; c++) {
            const bool ls = (__popc(lane & (int)lrow[c]) & 1) != 0;
            float v = ls ? -Ss[c] : Ss[c];
            v += __shfl_xor_sync(0xffffffffu, v, 16);
            v += __shfl_xor_sync(0xffffffffu, v, 8);
            v += __shfl_xor_sync(0xffffffffu, v, 4);
            v += __shfl_xor_sync(0xffffffffu, v, 2);
            v += __shfl_xor_sync(0xffffffffu, v, 1);
            ev[c] = v;
        }
    }

    if (lane == 0) {
        float t0 = (ev[0] + bias[0]) * scale[0];
        float t1 = (ev[1] + bias[1]) * scale[1];
        float t2 = (ev[2] + bias[2]) * scale[2];
        float t3 = (ev[3] + bias[3]) * scale[3];
        float m = fmaxf(fmaxf(t0, t1), fmaxf(t2, t3));
        float e0 = expf(t0 - m), e1 = expf(t1 - m), e2 = expf(t2 - m), e3 = expf(t3 - m);
        float inv = 1.0f / (e0 + e1 + e2 + e3);
        reinterpret_cast<float4*>(out)[b] =
            make_float4(e0 * inv, e1 * inv, e2 * inv, e3 * inv);
    }
}

extern "C" void kernel_launch(void* const* d_in, const int* in_sizes, int n_in,
                              void* d_out, int out_size) {
    const float* x       = (const float*)d_in[0];  // (B, NQ)
    const float* weights = (const float*)d_in[1];  // (NL, NQ, 3)
    const float* bias    = (const float*)d_in[2];  // (C,)
    const float* scale   = (const float*)d_in[3];  // (C,)
    float* out = (float*)d_out;                    // (B, C)

    rot_precompute_kernel<<<1, 64>>>(weights);
    // 8 warps per block (all 4 SMSPs fed), 2 blocks resident per SM
    vqc_kernel<<<BATCH / 8, 256>>>(x, bias, scale, out);
}

// round 12
// speedup vs baseline: 1.2163x; 1.0959x over previous
#include <cuda_runtime.h>

#define NQ 10
#define NL 4
#define NC 4
#define BATCH 2048

typedef unsigned long long u64;

// ============================================================================
// GF(2) linear-map tracking of the CNOT ring (all compile-time).
// Index bits: wire q <-> bit (9-q). Bits 5..9 = lane bits 0..4, bits 0..4 = local.
// Invariant: psi_phys[p] = sigma[F p], F = T^l at layer l.
// Gate on physical bit b: stored pair-XOR mask = column b of T^l,
//                         role(s) = <row_b(T^{-l}), s>.
// Measurement sign mask for bit b: row b of T^{-NL}.
// Layer-3 gates gauged by D = diag(w, conj(w)): legal because (T^{-3}T^3)=I
// commutes all layer-3 D's to the measurement, where diagonal phases vanish.
// ============================================================================

struct G10 { unsigned r[10]; };

__host__ __device__ constexpr G10 gid10() {
    G10 c{};
    for (int i = 0; i < 10; i++) c.r[i] = 1u << i;
    return c;
}
__host__ __device__ constexpr G10 gmul(const G10 a, const G10 b) {
    G10 c{};
    for (int i = 0; i < 10; i++) {
        unsigned m = 0;
        for (int j = 0; j < 10; j++)
            if ((a.r[i] >> j) & 1u) m ^= b.r[j];
        c.r[i] = m;
    }
    return c;
}
__host__ __device__ constexpr G10 makeT() {
    G10 c{};
    for (int i = 0; i < 8; i++) c.r[i] = (1u << i) | (1u << (i + 1));
    c.r[8] = 0x301u;
    c.r[9] = 0x201u;
    return c;
}
__host__ __device__ constexpr G10 makeTinv() {
    G10 c{};
    for (int i = 0; i < 9; i++) c.r[i] = (0x3FFu >> i) << i;
    c.r[9] = 0x1FFu;
    return c;
}
__host__ __device__ constexpr G10 gpow(const G10 a, int k) {
    G10 c = gid10();
    for (int t = 0; t < k; t++) c = gmul(a, c);
    return c;
}
__host__ __device__ constexpr bool iseq(const G10 a, const G10 b) {
    for (int i = 0; i < 10; i++) if (a.r[i] != b.r[i]) return false;
    return true;
}
static_assert(iseq(gmul(makeT(), makeTinv()), gid10()), "Tinv wrong");

__host__ __device__ constexpr unsigned colmask(const G10 m, int b) {
    unsigned v = 0;
    for (int i = 0; i < 10; i++) v |= ((m.r[i] >> b) & 1u) << i;
    return v;
}
__host__ __device__ constexpr unsigned gate_mask(int l, int q) {
    return colmask(gpow(makeT(), l), 9 - q);
}
__host__ __device__ constexpr unsigned gate_role(int l, int q) {
    return gpow(makeTinv(), l).r[9 - q];
}
__host__ __device__ constexpr unsigned meas_row(int wire) {
    return gpow(makeTinv(), NL).r[9 - wire];
}
__host__ __device__ constexpr int par10(unsigned v) {
    int p = 0;
    for (int i = 0; i < 10; i++) p ^= (int)((v >> i) & 1u);
    return p;
}

// ============================================================================
// Packed f32x2 helpers (Blackwell FFMA2)
// ============================================================================
__device__ __forceinline__ u64 pk(float lo, float hi) {
    u64 d;
    asm("mov.b64 %0, {%1, %2};" : "=l"(d) : "f"(lo), "f"(hi));
    return d;
}
__device__ __forceinline__ void upk(u64 v, float& lo, float& hi) {
    asm("mov.b64 {%0, %1}, %2;" : "=f"(lo), "=f"(hi) : "l"(v));
}
__device__ __forceinline__ u64 f2fma(u64 a, u64 b, u64 c) {
    u64 d;
    asm("fma.rn.f32x2 %0, %1, %2, %3;" : "=l"(d) : "l"(a), "l"(b), "l"(c));
    return d;
}
__device__ __forceinline__ u64 f2fma_neg(u64 a, u64 b, u64 c) {
    // c - a*b
    u64 m, d;
    asm("mul.rn.f32x2 %0, %1, %2;" : "=l"(m) : "l"(a), "l"(b));
    asm("sub.rn.f32x2 %0, %1, %2;" : "=l"(d) : "l"(c), "l"(m));
    return d;
}
__device__ __forceinline__ u64 f2mul(u64 a, u64 b) {
    u64 d;
    asm("mul.rn.f32x2 %0, %1, %2;" : "=l"(d) : "l"(a), "l"(b));
    return d;
}
__device__ __forceinline__ u64 swap2(u64 v) { return (v >> 32) | (v << 32); }
__device__ __forceinline__ u64 shfl64(u64 v, int m) {
    return __shfl_xor_sync(0xffffffffu, v, m);
}

// ============================================================================
// Generalized 1q SU(2) gate, sign-unified roles (8 packed ops / group):
// out_r = Ar*sr - sAi*si + sBr*or - Bi*oi
// out_i = Ar*si + sAi*sr + sBr*oi + Bi*or
// sAi = sigma*Ai, sBr = sigma*Br, sigma = (-1)^(par(lane&RL) ^ par(j&RJ))
// ============================================================================
template <int LM, int JM, int RL, int RJ>
__device__ __forceinline__ void gate_apply(u64* Vr, u64* Vi, int lane,
                                           float Ar, float Ai, float Br, float Bi) {
    constexpr int JH = JM >> 1, JL = JM & 1;
    constexpr int JHB = JH & (-JH);
    constexpr int RJH = RJ >> 1, RJL = RJ & 1;

    const bool rl = (RL != 0) && ((__popc(lane & RL) & 1) != 0);
    const float aAi = rl ? -Ai : Ai;
    const float aBr = rl ? -Br : Br;

    const u64 PAr  = pk(Ar, Ar);
    const u64 PBi  = pk(Bi, Bi);
    const u64 PBiN = pk(-Bi, -Bi);
    const u64 PsAi0  = pk(aAi, RJL ? -aAi : aAi);
    const u64 PsAiN0 = pk(-aAi, RJL ? aAi : -aAi);
    const u64 PsBr0  = pk(aBr, RJL ? -aBr : aBr);
    u64 PsAi1 = PsAi0, PsAiN1 = PsAiN0, PsBr1 = PsBr0;
    if (RJH != 0) {
        PsAi1  = pk(-aAi, RJL ? aAi : -aAi);
        PsAiN1 = pk(aAi, RJL ? -aAi : aAi);
        PsBr1  = pk(-aBr, RJL ? aBr : -aBr);
    }

#pragma unroll
    for (int g = 0; g < 16; g++) {
        if (JH != 0 && (g & JHB) != 0) continue;  // one rep per {g, g^JH} orbit
        const int pg = g ^ JH;
        const u64 sr = Vr[g], si = Vi[g];
        u64 or_g, oi_g;
        u64 sr2 = 0, si2 = 0, or_p = 0, oi_p = 0;
        if (LM != 0) { or_g = shfl64(Vr[pg], LM); oi_g = shfl64(Vi[pg], LM); }
        else         { or_g = Vr[pg];             oi_g = Vi[pg]; }
        if (JH != 0) {
            sr2 = Vr[pg]; si2 = Vi[pg];
            if (LM != 0) { or_p = shfl64(Vr[g], LM); oi_p = shfl64(Vi[g], LM); }
            else         { or_p = sr;                oi_p = si; }
        }
        if (JL != 0) {
            or_g = swap2(or_g); oi_g = swap2(oi_g);
            if (JH != 0) { or_p = swap2(or_p); oi_p = swap2(oi_p); }
        }
        {
            const bool v = (__popc(g & RJH) & 1) != 0;
            const u64 pAi = v ? PsAi1 : PsAi0, pAiN = v ? PsAiN1 : PsAiN0;
            const u64 pBr = v ? PsBr1 : PsBr0;
            Vr[g] = f2fma(PAr, sr, f2fma(pAiN, si, f2fma(pBr, or_g, f2mul(PBiN, oi_g))));
            Vi[g] = f2fma(PAr, si, f2fma(pAi,  sr, f2fma(pBr, oi_g, f2mul(PBi,  or_g))));
        }
        if (JH != 0) {
            const bool v = (__popc(pg & RJH) & 1) != 0;
            const u64 pAi = v ? PsAi1 : PsAi0, pAiN = v ? PsAiN1 : PsAiN0;
            const u64 pBr = v ? PsBr1 : PsBr0;
            Vr[pg] = f2fma(PAr, sr2, f2fma(pAiN, si2, f2fma(pBr, or_p, f2mul(PBiN, oi_p))));
            Vi[pg] = f2fma(PAr, si2, f2fma(pAi,  sr2, f2fma(pBr, oi_p, f2mul(PBi,  or_p))));
        }
    }
}

// ============================================================================
// Gauged gate (A real) for the final layer — 6 packed ops / group.
// ============================================================================
template <int LM, int JM, int RL, int RJ>
__device__ __forceinline__ void gate_apply_gauged(u64* Vr, u64* Vi, int lane,
                                                  float Ar, float Br, float Bi) {
    constexpr int JH = JM >> 1, JL = JM & 1;
    constexpr int JHB = JH & (-JH);
    constexpr int RJH = RJ >> 1, RJL = RJ & 1;

    const bool rl = (RL != 0) && ((__popc(lane & RL) & 1) != 0);
    const float aBr = rl ? -Br : Br;

    const u64 PAr  = pk(Ar, Ar);
    const u64 PBi  = pk(Bi, Bi);
    const u64 PBiN = pk(-Bi, -Bi);
    const u64 PsBr0 = pk(aBr, RJL ? -aBr : aBr);
    u64 PsBr1 = PsBr0;
    if (RJH != 0) PsBr1 = pk(-aBr, RJL ? aBr : -aBr);

#pragma unroll
    for (int g = 0; g < 16; g++) {
        if (JH != 0 && (g & JHB) != 0) continue;
        const int pg = g ^ JH;
        const u64 sr = Vr[g], si = Vi[g];
        u64 or_g, oi_g;
        u64 sr2 = 0, si2 = 0, or_p = 0, oi_p = 0;
        if (LM != 0) { or_g = shfl64(Vr[pg], LM); oi_g = shfl64(Vi[pg], LM); }
        else         { or_g = Vr[pg];             oi_g = Vi[pg]; }
        if (JH != 0) {
            sr2 = Vr[pg]; si2 = Vi[pg];
            if (LM != 0) { or_p = shfl64(Vr[g], LM); oi_p = shfl64(Vi[g], LM); }
            else         { or_p = sr;                oi_p = si; }
        }
        if (JL != 0) {
            or_g = swap2(or_g); oi_g = swap2(oi_g);
            if (JH != 0) { or_p = swap2(or_p); oi_p = swap2(oi_p); }
        }
        {
            const bool v = (__popc(g & RJH) & 1) != 0;
            const u64 pBr = v ? PsBr1 : PsBr0;
            Vr[g] = f2fma(PAr, sr, f2fma(pBr, or_g, f2mul(PBiN, oi_g)));
            Vi[g] = f2fma(PAr, si, f2fma(pBr, oi_g, f2mul(PBi,  or_g)));
        }
        if (JH != 0) {
            const bool v = (__popc(pg & RJH) & 1) != 0;
            const u64 pBr = v ? PsBr1 : PsBr0;
            Vr[pg] = f2fma(PAr, sr2, f2fma(pBr, or_p, f2mul(PBiN, oi_p)));
            Vi[pg] = f2fma(PAr, si2, f2fma(pBr, oi_p, f2mul(PBi,  or_p)));
        }
    }
}

// ============================================================================
// Kernel: lane-parallel coefficient factory (prologue) + register state sim.
// Shared table per warp: 40 entries x 4 floats:
//   [0..29]  = gate coefficients, idx = (l-1)*10 + q, l in {1,2,3}
//              l<3: (Ar, Ai, Br, Bi) ; l=3 gauged: (Ar, 0, Br, Bi)
//   [30..39] = layer-0 column-0 (ar, ai, br, bi) per wire q
// ============================================================================
__global__ void __launch_bounds__(256, 2)
vqc_kernel(const float* __restrict__ x,
           const float* __restrict__ wt,
           const float* __restrict__ bias,
           const float* __restrict__ scale,
           float* __restrict__ out) {
    __shared__ float scoef[8 * 40 * 4];

    const int lane = threadIdx.x & 31;
    const int warp = threadIdx.x >> 5;
    const int b = (blockIdx.x * blockDim.x + threadIdx.x) >> 5;
    float* wc = scoef + warp * 160;

    // ---- Prologue: lane i computes gate i's coefficients (parallel) ----
    if (lane < 30) {
        const int l = 1 + lane / 10;
        const int q = lane - (l - 1) * 10;
        float xs_, xc_;
        sincosf(0.5f * x[b * NQ + q], &xs_, &xc_);

        const float* wp = wt + (l * NQ + q) * 3;
        const float phi = wp[0], th = wp[1], om = wp[2];
        float spo, cpo, spm, cpm, st, ct;
        sincosf(0.5f * (phi + om), &spo, &cpo);
        sincosf(0.5f * (phi - om), &spm, &cpm);
        sincosf(0.5f * th, &st, &ct);

        // Fused M = Rot*RX, columns {m00 (=A), m01 (=B)}:
        float Ar =  xc_ * cpo * ct - xs_ * spm * st;
        float Ai = -xc_ * spo * ct + xs_ * cpm * st;
        float Br = -xs_ * spo * ct - xc_ * cpm * st;
        float Bi = -xs_ * cpo * ct - xc_ * spm * st;
        if (l == 3) {
            // Gauge: D = diag(w, conj(w)), w = conj(A)/|A| -> A real
            const float n2  = Ar * Ar + Ai * Ai;
            const float inv = rsqrtf(n2 + 1e-30f);
            const float wr  =  Ar * inv;
            const float wi  = -Ai * inv;
            const float B2r = wr * Br - wi * Bi;
            Bi = wr * Bi + wi * Br;
            Br = B2r;
            Ar = n2 * inv;
            Ai = 0.0f;
        }
        wc[lane * 4 + 0] = Ar;
        wc[lane * 4 + 1] = Ai;
        wc[lane * 4 + 2] = Br;
        wc[lane * 4 + 3] = Bi;

        if (lane < 10) {
            // Layer-0 column 0 (a = M00, b = M10) for wire q = lane
            const float* w0 = wt + q * 3;
            const float p0 = w0[0], t0 = w0[1], o0 = w0[2];
            float spo0, cpo0, spm0, cpm0, st0, ct0;
            sincosf(0.5f * (p0 + o0), &spo0, &cpo0);
            sincosf(0.5f * (p0 - o0), &spm0, &cpm0);
            sincosf(0.5f * t0, &st0, &ct0);
            wc[(30 + q) * 4 + 0] =  xc_ * cpo0 * ct0 - xs_ * spm0 * st0;
            wc[(30 + q) * 4 + 1] = -xc_ * spo0 * ct0 + xs_ * cpm0 * st0;
            wc[(30 + q) * 4 + 2] =  xc_ * cpm0 * st0 + xs_ * spo0 * ct0;
            wc[(30 + q) * 4 + 3] = -xc_ * spm0 * st0 - xs_ * cpo0 * ct0;
        }
    }
    __syncwarp();

    // ---- Layer 0 via product-state construction ----
    u64 Vr[16], Vi[16];

    // Lane factor: wires 0..4 <-> lane bits 4..0
    float Lfr = 1.0f, Lfi = 0.0f;
#pragma unroll
    for (int q = 0; q < 5; q++) {
        const float4 v = *(const float4*)(wc + (30 + q) * 4);
        const bool bit = ((lane >> (4 - q)) & 1) != 0;
        const float fr = bit ? v.z : v.x;
        const float fi = bit ? v.w : v.y;
        const float nr = Lfr * fr - Lfi * fi;
        const float ni = Lfr * fi + Lfi * fr;
        Lfr = nr; Lfi = ni;
    }

    // Local wires 5..9 <-> local bits 4..0 (wire q -> local bit 9-q)
    float lar[5], lai[5], lbr[5], lbi[5];
#pragma unroll
    for (int m = 0; m < 5; m++) {
        const float4 v = *(const float4*)(wc + (30 + (9 - m)) * 4);
        lar[m] = v.x; lai[m] = v.y; lbr[m] = v.z; lbi[m] = v.w;
    }

    {
        const float e0r = Lfr * lar[0] - Lfi * lai[0];
        const float e0i = Lfr * lai[0] + Lfi * lar[0];
        const float e1r = Lfr * lbr[0] - Lfi * lbi[0];
        const float e1i = Lfr * lbi[0] + Lfi * lbr[0];
        Vr[0] = pk(e0r, e1r);
        Vi[0] = pk(e0i, e1i);
    }
#pragma unroll
    for (int m = 1; m < 5; m++) {
        const u64 Ar2 = pk(lar[m], lar[m]), Ai2 = pk(lai[m], lai[m]);
        const u64 Br2 = pk(lbr[m], lbr[m]), Bi2 = pk(lbi[m], lbi[m]);
        const int half = 1 << (m - 1);
#pragma unroll
        for (int g = 0; g < 16; g++) {
            if (g >= half) continue;
            const u64 r = Vr[g], i = Vi[g];
            Vr[g | half] = f2fma_neg(i, Bi2, f2mul(r, Br2));
            Vi[g | half] = f2fma(r, Bi2, f2mul(i, Br2));
            Vr[g]        = f2fma_neg(i, Ai2, f2mul(r, Ar2));
            Vi[g]        = f2fma(r, Ai2, f2mul(i, Ar2));
        }
    }

#define APPLY_GATE(L, Q)                                                        \
    do {                                                                        \
        const float4 v_ = *(const float4*)(wc + (((L) - 1) * 10 + (Q)) * 4);    \
        constexpr unsigned gm_ = gate_mask(L, Q);                               \
        constexpr unsigned gr_ = gate_role(L, Q);                               \
        gate_apply<(int)((gm_ >> 5) & 31u), (int)(gm_ & 31u),                   \
                   (int)((gr_ >> 5) & 31u), (int)(gr_ & 31u)>(                  \
            Vr, Vi, lane, v_.x, v_.y, v_.z, v_.w);                              \
    } while (0)

#define APPLY_GATE_GAUGED(L, Q)                                                 \
    do {                                                                        \
        const float4 v_ = *(const float4*)(wc + (((L) - 1) * 10 + (Q)) * 4);    \
        constexpr unsigned gm_ = gate_mask(L, Q);                               \
        constexpr unsigned gr_ = gate_role(L, Q);                               \
        gate_apply_gauged<(int)((gm_ >> 5) & 31u), (int)(gm_ & 31u),            \
                          (int)((gr_ >> 5) & 31u), (int)(gr_ & 31u)>(           \
            Vr, Vi, lane, v_.x, v_.z, v_.w);                                    \
    } while (0)

#define APPLY_LAYER(L)                                                          \
    APPLY_GATE(L, 0); APPLY_GATE(L, 1); APPLY_GATE(L, 2); APPLY_GATE(L, 3);     \
    APPLY_GATE(L, 4); APPLY_GATE(L, 5); APPLY_GATE(L, 6); APPLY_GATE(L, 7);     \
    APPLY_GATE(L, 8); APPLY_GATE(L, 9);

    APPLY_LAYER(1)
    APPLY_LAYER(2)

    APPLY_GATE_GAUGED(3, 0); APPLY_GATE_GAUGED(3, 1);
    APPLY_GATE_GAUGED(3, 2); APPLY_GATE_GAUGED(3, 3);
    APPLY_GATE_GAUGED(3, 4); APPLY_GATE_GAUGED(3, 5);
    APPLY_GATE_GAUGED(3, 6); APPLY_GATE_GAUGED(3, 7);
    APPLY_GATE_GAUGED(3, 8); APPLY_GATE_GAUGED(3, 9);

#undef APPLY_LAYER
#undef APPLY_GATE
#undef APPLY_GATE_GAUGED

    // Single-pass measurement: 4 signed sums over probabilities.
    constexpr unsigned rows0 = meas_row(0), rows1 = meas_row(1);
    constexpr unsigned rows2 = meas_row(2), rows3 = meas_row(3);
    float S0 = 0.f, S1 = 0.f, S2 = 0.f, S3 = 0.f;
#pragma unroll
    for (int g = 0; g < 16; g++) {
        u64 P = f2fma(Vr[g], Vr[g], f2mul(Vi[g], Vi[g]));
        float plo, phi_;
        upk(P, plo, phi_);
#pragma unroll
        for (int h = 0; h < 2; h++) {
            const int j = 2 * g + h;
            const float pv = h ? phi_ : plo;
            S0 += par10(j & (rows0 & 31u)) ? -pv : pv;
            S1 += par10(j & (rows1 & 31u)) ? -pv : pv;
            S2 += par10(j & (rows2 & 31u)) ? -pv : pv;
            S3 += par10(j & (rows3 & 31u)) ? -pv : pv;
        }
    }
    float ev[NC];
    {
        const unsigned lrow[NC] = {rows0 >> 5, rows1 >> 5, rows2 >> 5, rows3 >> 5};
        float Ss[NC] = {S0, S1, S2, S3};
#pragma unroll
        for (int c = 0; c < NC; c++) {
            const bool ls = (__popc(lane & (int)lrow[c]) & 1) != 0;
            float v = ls ? -Ss[c] : Ss[c];
            v += __shfl_xor_sync(0xffffffffu, v, 16);
            v += __shfl_xor_sync(0xffffffffu, v, 8);
            v += __shfl_xor_sync(0xffffffffu, v, 4);
            v += __shfl_xor_sync(0xffffffffu, v, 2);
            v += __shfl_xor_sync(0xffffffffu, v, 1);
            ev[c] = v;
        }
    }

    if (lane == 0) {
        float t0 = (ev[0] + bias[0]) * scale[0];
        float t1 = (ev[1] + bias[1]) * scale[1];
        float t2 = (ev[2] + bias[2]) * scale[2];
        float t3 = (ev[3] + bias[3]) * scale[3];
        float m = fmaxf(fmaxf(t0, t1), fmaxf(t2, t3));
        float e0 = expf(t0 - m), e1 = expf(t1 - m), e2 = expf(t2 - m), e3 = expf(t3 - m);
        float inv = 1.0f / (e0 + e1 + e2 + e3);
        reinterpret_cast<float4*>(out)[b] =
            make_float4(e0 * inv, e1 * inv, e2 * inv, e3 * inv);
    }
}

extern "C" void kernel_launch(void* const* d_in, const int* in_sizes, int n_in,
                              void* d_out, int out_size) {
    const float* x       = (const float*)d_in[0];  // (B, NQ)
    const float* weights = (const float*)d_in[1];  // (NL, NQ, 3)
    const float* bias    = (const float*)d_in[2];  // (C,)
    const float* scale   = (const float*)d_in[3];  // (C,)
    float* out = (float*)d_out;                    // (B, C)

    // Single kernel: coefficient factory folded into the prologue.
    vqc_kernel<<<BATCH / 8, 256>>>(x, weights, bias, scale, out);
}

// round 13
// speedup vs baseline: 1.3097x; 1.0768x over previous
#include <cuda_runtime.h>

#define NQ 10
#define NL 4
#define NC 4
#define BATCH 2048

typedef unsigned long long u64;

// ============================================================================
// GF(2) linear-map tracking of the CNOT ring (all compile-time).
// Index bits: wire q <-> bit (9-q). Bits 5..9 = lane bits 0..4, bits 0..4 = local.
// Invariant: psi_phys[p] = sigma[F p], F = T^l at layer l.
// Gate on physical bit b: stored pair-XOR mask = column b of T^l,
//                         role(s) = <row_b(T^{-l}), s>.
// Measurement sign mask for bit b: row b of T^{-NL}.
// Layer-3 gates gauged by D = diag(w, conj(w)): legal because (T^{-3}T^3)=I
// commutes all layer-3 D's to the measurement, where diagonal phases vanish.
// Gates within a layer commute (different physical wires) -> reordered to
// interleave lane-exchange gates with local gates for scheduling overlap.
// ============================================================================

struct G10 { unsigned r[10]; };

__host__ __device__ constexpr G10 gid10() {
    G10 c{};
    for (int i = 0; i < 10; i++) c.r[i] = 1u << i;
    return c;
}
__host__ __device__ constexpr G10 gmul(const G10 a, const G10 b) {
    G10 c{};
    for (int i = 0; i < 10; i++) {
        unsigned m = 0;
        for (int j = 0; j < 10; j++)
            if ((a.r[i] >> j) & 1u) m ^= b.r[j];
        c.r[i] = m;
    }
    return c;
}
__host__ __device__ constexpr G10 makeT() {
    G10 c{};
    for (int i = 0; i < 8; i++) c.r[i] = (1u << i) | (1u << (i + 1));
    c.r[8] = 0x301u;
    c.r[9] = 0x201u;
    return c;
}
__host__ __device__ constexpr G10 makeTinv() {
    G10 c{};
    for (int i = 0; i < 9; i++) c.r[i] = (0x3FFu >> i) << i;
    c.r[9] = 0x1FFu;
    return c;
}
__host__ __device__ constexpr G10 gpow(const G10 a, int k) {
    G10 c = gid10();
    for (int t = 0; t < k; t++) c = gmul(a, c);
    return c;
}
__host__ __device__ constexpr bool iseq(const G10 a, const G10 b) {
    for (int i = 0; i < 10; i++) if (a.r[i] != b.r[i]) return false;
    return true;
}
static_assert(iseq(gmul(makeT(), makeTinv()), gid10()), "Tinv wrong");

__host__ __device__ constexpr unsigned colmask(const G10 m, int b) {
    unsigned v = 0;
    for (int i = 0; i < 10; i++) v |= ((m.r[i] >> b) & 1u) << i;
    return v;
}
__host__ __device__ constexpr unsigned gate_mask(int l, int q) {
    return colmask(gpow(makeT(), l), 9 - q);
}
__host__ __device__ constexpr unsigned gate_role(int l, int q) {
    return gpow(makeTinv(), l).r[9 - q];
}
__host__ __device__ constexpr unsigned meas_row(int wire) {
    return gpow(makeTinv(), NL).r[9 - wire];
}
__host__ __device__ constexpr int par10(unsigned v) {
    int p = 0;
    for (int i = 0; i < 10; i++) p ^= (int)((v >> i) & 1u);
    return p;
}

// ============================================================================
// Packed f32x2 helpers (Blackwell FFMA2)
// ============================================================================
__device__ __forceinline__ u64 pk(float lo, float hi) {
    u64 d;
    asm("mov.b64 %0, {%1, %2};" : "=l"(d) : "f"(lo), "f"(hi));
    return d;
}
__device__ __forceinline__ void upk(u64 v, float& lo, float& hi) {
    asm("mov.b64 {%0, %1}, %2;" : "=f"(lo), "=f"(hi) : "l"(v));
}
__device__ __forceinline__ u64 f2fma(u64 a, u64 b, u64 c) {
    u64 d;
    asm("fma.rn.f32x2 %0, %1, %2, %3;" : "=l"(d) : "l"(a), "l"(b), "l"(c));
    return d;
}
__device__ __forceinline__ u64 f2fma_neg(u64 a, u64 b, u64 c) {
    // c - a*b
    u64 m, d;
    asm("mul.rn.f32x2 %0, %1, %2;" : "=l"(m) : "l"(a), "l"(b));
    asm("sub.rn.f32x2 %0, %1, %2;" : "=l"(d) : "l"(c), "l"(m));
    return d;
}
__device__ __forceinline__ u64 f2mul(u64 a, u64 b) {
    u64 d;
    asm("mul.rn.f32x2 %0, %1, %2;" : "=l"(d) : "l"(a), "l"(b));
    return d;
}
__device__ __forceinline__ u64 swap2(u64 v) { return (v >> 32) | (v << 32); }
__device__ __forceinline__ u64 shfl64(u64 v, int m) {
    return __shfl_xor_sync(0xffffffffu, v, m);
}

// ============================================================================
// Generalized 1q SU(2) gate, sign-unified roles (8 packed ops / group).
// ============================================================================
template <int LM, int JM, int RL, int RJ>
__device__ __forceinline__ void gate_apply(u64* Vr, u64* Vi, int lane,
                                           float Ar, float Ai, float Br, float Bi) {
    constexpr int JH = JM >> 1, JL = JM & 1;
    constexpr int JHB = JH & (-JH);
    constexpr int RJH = RJ >> 1, RJL = RJ & 1;

    const bool rl = (RL != 0) && ((__popc(lane & RL) & 1) != 0);
    const float aAi = rl ? -Ai : Ai;
    const float aBr = rl ? -Br : Br;

    const u64 PAr  = pk(Ar, Ar);
    const u64 PBi  = pk(Bi, Bi);
    const u64 PBiN = pk(-Bi, -Bi);
    const u64 PsAi0  = pk(aAi, RJL ? -aAi : aAi);
    const u64 PsAiN0 = pk(-aAi, RJL ? aAi : -aAi);
    const u64 PsBr0  = pk(aBr, RJL ? -aBr : aBr);
    u64 PsAi1 = PsAi0, PsAiN1 = PsAiN0, PsBr1 = PsBr0;
    if (RJH != 0) {
        PsAi1  = pk(-aAi, RJL ? aAi : -aAi);
        PsAiN1 = pk(aAi, RJL ? -aAi : aAi);
        PsBr1  = pk(-aBr, RJL ? aBr : -aBr);
    }

#pragma unroll
    for (int g = 0; g < 16; g++) {
        if (JH != 0 && (g & JHB) != 0) continue;  // one rep per {g, g^JH} orbit
        const int pg = g ^ JH;
        const u64 sr = Vr[g], si = Vi[g];
        u64 or_g, oi_g;
        u64 sr2 = 0, si2 = 0, or_p = 0, oi_p = 0;
        if (LM != 0) { or_g = shfl64(Vr[pg], LM); oi_g = shfl64(Vi[pg], LM); }
        else         { or_g = Vr[pg];             oi_g = Vi[pg]; }
        if (JH != 0) {
            sr2 = Vr[pg]; si2 = Vi[pg];
            if (LM != 0) { or_p = shfl64(Vr[g], LM); oi_p = shfl64(Vi[g], LM); }
            else         { or_p = sr;                oi_p = si; }
        }
        if (JL != 0) {
            or_g = swap2(or_g); oi_g = swap2(oi_g);
            if (JH != 0) { or_p = swap2(or_p); oi_p = swap2(oi_p); }
        }
        {
            const bool v = (__popc(g & RJH) & 1) != 0;
            const u64 pAi = v ? PsAi1 : PsAi0, pAiN = v ? PsAiN1 : PsAiN0;
            const u64 pBr = v ? PsBr1 : PsBr0;
            Vr[g] = f2fma(PAr, sr, f2fma(pAiN, si, f2fma(pBr, or_g, f2mul(PBiN, oi_g))));
            Vi[g] = f2fma(PAr, si, f2fma(pAi,  sr, f2fma(pBr, oi_g, f2mul(PBi,  or_g))));
        }
        if (JH != 0) {
            const bool v = (__popc(pg & RJH) & 1) != 0;
            const u64 pAi = v ? PsAi1 : PsAi0, pAiN = v ? PsAiN1 : PsAiN0;
            const u64 pBr = v ? PsBr1 : PsBr0;
            Vr[pg] = f2fma(PAr, sr2, f2fma(pAiN, si2, f2fma(pBr, or_p, f2mul(PBiN, oi_p))));
            Vi[pg] = f2fma(PAr, si2, f2fma(pAi,  sr2, f2fma(pBr, oi_p, f2mul(PBi,  or_p))));
        }
    }
}

// ============================================================================
// Gauged gate (A real) for the final layer — 6 packed ops / group.
// ============================================================================
template <int LM, int JM, int RL, int RJ>
__device__ __forceinline__ void gate_apply_gauged(u64* Vr, u64* Vi, int lane,
                                                  float Ar, float Br, float Bi) {
    constexpr int JH = JM >> 1, JL = JM & 1;
    constexpr int JHB = JH & (-JH);
    constexpr int RJH = RJ >> 1, RJL = RJ & 1;

    const bool rl = (RL != 0) && ((__popc(lane & RL) & 1) != 0);
    const float aBr = rl ? -Br : Br;

    const u64 PAr  = pk(Ar, Ar);
    const u64 PBi  = pk(Bi, Bi);
    const u64 PBiN = pk(-Bi, -Bi);
    const u64 PsBr0 = pk(aBr, RJL ? -aBr : aBr);
    u64 PsBr1 = PsBr0;
    if (RJH != 0) PsBr1 = pk(-aBr, RJL ? aBr : -aBr);

#pragma unroll
    for (int g = 0; g < 16; g++) {
        if (JH != 0 && (g & JHB) != 0) continue;
        const int pg = g ^ JH;
        const u64 sr = Vr[g], si = Vi[g];
        u64 or_g, oi_g;
        u64 sr2 = 0, si2 = 0, or_p = 0, oi_p = 0;
        if (LM != 0) { or_g = shfl64(Vr[pg], LM); oi_g = shfl64(Vi[pg], LM); }
        else         { or_g = Vr[pg];             oi_g = Vi[pg]; }
        if (JH != 0) {
            sr2 = Vr[pg]; si2 = Vi[pg];
            if (LM != 0) { or_p = shfl64(Vr[g], LM); oi_p = shfl64(Vi[g], LM); }
            else         { or_p = sr;                oi_p = si; }
        }
        if (JL != 0) {
            or_g = swap2(or_g); oi_g = swap2(oi_g);
            if (JH != 0) { or_p = swap2(or_p); oi_p = swap2(oi_p); }
        }
        {
            const bool v = (__popc(g & RJH) & 1) != 0;
            const u64 pBr = v ? PsBr1 : PsBr0;
            Vr[g] = f2fma(PAr, sr, f2fma(pBr, or_g, f2mul(PBiN, oi_g)));
            Vi[g] = f2fma(PAr, si, f2fma(pBr, oi_g, f2mul(PBi,  or_g)));
        }
        if (JH != 0) {
            const bool v = (__popc(pg & RJH) & 1) != 0;
            const u64 pBr = v ? PsBr1 : PsBr0;
            Vr[pg] = f2fma(PAr, sr2, f2fma(pBr, or_p, f2mul(PBiN, oi_p)));
            Vi[pg] = f2fma(PAr, si2, f2fma(pBr, oi_p, f2mul(PBi,  or_p)));
        }
    }
}

// ============================================================================
// Kernel: lane-parallel coefficient factory (prologue) + register state sim.
// ============================================================================
__global__ void __launch_bounds__(256, 2)
vqc_kernel(const float* __restrict__ x,
           const float* __restrict__ wt,
           const float* __restrict__ bias,
           const float* __restrict__ scale,
           float* __restrict__ out) {
    __shared__ float scoef[8 * 40 * 4];

    const int lane = threadIdx.x & 31;
    const int warp = threadIdx.x >> 5;
    const int b = (blockIdx.x * blockDim.x + threadIdx.x) >> 5;
    float* wc = scoef + warp * 160;

    // ---- Prologue: lane i computes gate i's coefficients (parallel) ----
    if (lane < 30) {
        const int l = 1 + lane / 10;
        const int q = lane - (l - 1) * 10;
        float xs_, xc_;
        __sincosf(0.5f * x[b * NQ + q], &xs_, &xc_);

        const float* wp = wt + (l * NQ + q) * 3;
        const float phi = wp[0], th = wp[1], om = wp[2];
        float spo, cpo, spm, cpm, st, ct;
        __sincosf(0.5f * (phi + om), &spo, &cpo);
        __sincosf(0.5f * (phi - om), &spm, &cpm);
        __sincosf(0.5f * th, &st, &ct);

        // Fused M = Rot*RX, columns {m00 (=A), m01 (=B)}:
        float Ar =  xc_ * cpo * ct - xs_ * spm * st;
        float Ai = -xc_ * spo * ct + xs_ * cpm * st;
        float Br = -xs_ * spo * ct - xc_ * cpm * st;
        float Bi = -xs_ * cpo * ct - xc_ * spm * st;
        if (l == 3) {
            // Gauge: D = diag(w, conj(w)), w = conj(A)/|A| -> A real
            const float n2  = Ar * Ar + Ai * Ai;
            const float inv = rsqrtf(n2 + 1e-30f);
            const float wr  =  Ar * inv;
            const float wi  = -Ai * inv;
            const float B2r = wr * Br - wi * Bi;
            Bi = wr * Bi + wi * Br;
            Br = B2r;
            Ar = n2 * inv;
            Ai = 0.0f;
        }
        wc[lane * 4 + 0] = Ar;
        wc[lane * 4 + 1] = Ai;
        wc[lane * 4 + 2] = Br;
        wc[lane * 4 + 3] = Bi;

        if (lane < 10) {
            // Layer-0 column 0 (a = M00, b = M10) for wire q = lane
            const float* w0 = wt + q * 3;
            const float p0 = w0[0], t0 = w0[1], o0 = w0[2];
            float spo0, cpo0, spm0, cpm0, st0, ct0;
            __sincosf(0.5f * (p0 + o0), &spo0, &cpo0);
            __sincosf(0.5f * (p0 - o0), &spm0, &cpm0);
            __sincosf(0.5f * t0, &st0, &ct0);
            wc[(30 + q) * 4 + 0] =  xc_ * cpo0 * ct0 - xs_ * spm0 * st0;
            wc[(30 + q) * 4 + 1] = -xc_ * spo0 * ct0 + xs_ * cpm0 * st0;
            wc[(30 + q) * 4 + 2] =  xc_ * cpm0 * st0 + xs_ * spo0 * ct0;
            wc[(30 + q) * 4 + 3] = -xc_ * spm0 * st0 - xs_ * cpo0 * ct0;
        }
    }
    __syncwarp();

    // ---- Layer 0 via product-state construction ----
    u64 Vr[16], Vi[16];

    // Lane factor: wires 0..4 <-> lane bits 4..0
    float Lfr = 1.0f, Lfi = 0.0f;
#pragma unroll
    for (int q = 0; q < 5; q++) {
        const float4 v = *(const float4*)(wc + (30 + q) * 4);
        const bool bit = ((lane >> (4 - q)) & 1) != 0;
        const float fr = bit ? v.z : v.x;
        const float fi = bit ? v.w : v.y;
        const float nr = Lfr * fr - Lfi * fi;
        const float ni = Lfr * fi + Lfi * fr;
        Lfr = nr; Lfi = ni;
    }

    // Local wires 5..9 <-> local bits 4..0 (wire q -> local bit 9-q)
    float lar[5], lai[5], lbr[5], lbi[5];
#pragma unroll
    for (int m = 0; m < 5; m++) {
        const float4 v = *(const float4*)(wc + (30 + (9 - m)) * 4);
        lar[m] = v.x; lai[m] = v.y; lbr[m] = v.z; lbi[m] = v.w;
    }

    {
        const float e0r = Lfr * lar[0] - Lfi * lai[0];
        const float e0i = Lfr * lai[0] + Lfi * lar[0];
        const float e1r = Lfr * lbr[0] - Lfi * lbi[0];
        const float e1i = Lfr * lbi[0] + Lfi * lbr[0];
        Vr[0] = pk(e0r, e1r);
        Vi[0] = pk(e0i, e1i);
    }
#pragma unroll
    for (int m = 1; m < 5; m++) {
        const u64 Ar2 = pk(lar[m], lar[m]), Ai2 = pk(lai[m], lai[m]);
        const u64 Br2 = pk(lbr[m], lbr[m]), Bi2 = pk(lbi[m], lbi[m]);
        const int half = 1 << (m - 1);
#pragma unroll
        for (int g = 0; g < 16; g++) {
            if (g >= half) continue;
            const u64 r = Vr[g], i = Vi[g];
            Vr[g | half] = f2fma_neg(i, Bi2, f2mul(r, Br2));
            Vi[g | half] = f2fma(r, Bi2, f2mul(i, Br2));
            Vr[g]        = f2fma_neg(i, Ai2, f2mul(r, Ar2));
            Vi[g]        = f2fma(r, Ai2, f2mul(i, Ar2));
        }
    }

#define APPLY_GATE(L, Q)                                                        \
    do {                                                                        \
        const float4 v_ = *(const float4*)(wc + (((L) - 1) * 10 + (Q)) * 4);    \
        constexpr unsigned gm_ = gate_mask(L, Q);                               \
        constexpr unsigned gr_ = gate_role(L, Q);                               \
        gate_apply<(int)((gm_ >> 5) & 31u), (int)(gm_ & 31u),                   \
                   (int)((gr_ >> 5) & 31u), (int)(gr_ & 31u)>(                  \
            Vr, Vi, lane, v_.x, v_.y, v_.z, v_.w);                              \
    } while (0)

#define APPLY_GATE_GAUGED(L, Q)                                                 \
    do {                                                                        \
        const float4 v_ = *(const float4*)(wc + (((L) - 1) * 10 + (Q)) * 4);    \
        constexpr unsigned gm_ = gate_mask(L, Q);                               \
        constexpr unsigned gr_ = gate_role(L, Q);                               \
        gate_apply_gauged<(int)((gm_ >> 5) & 31u), (int)(gm_ & 31u),            \
                          (int)((gr_ >> 5) & 31u), (int)(gr_ & 31u)>(           \
            Vr, Vi, lane, v_.x, v_.z, v_.w);                                    \
    } while (0)

    // Interleaved order (gates within a layer commute — lane/local alternated):
    // L1 lane: q0,5,6,7,8,9  local: q1,2,3,4
    APPLY_GATE(1, 0); APPLY_GATE(1, 1); APPLY_GATE(1, 5); APPLY_GATE(1, 2);
    APPLY_GATE(1, 6); APPLY_GATE(1, 3); APPLY_GATE(1, 7); APPLY_GATE(1, 4);
    APPLY_GATE(1, 8); APPLY_GATE(1, 9);
    // L2 lane: q0,1,5,6,7,8,9  local: q2,3,4
    APPLY_GATE(2, 0); APPLY_GATE(2, 2); APPLY_GATE(2, 1); APPLY_GATE(2, 3);
    APPLY_GATE(2, 5); APPLY_GATE(2, 4); APPLY_GATE(2, 6); APPLY_GATE(2, 7);
    APPLY_GATE(2, 8); APPLY_GATE(2, 9);
    // L3 lane: q0,1,2,5,6,7,8,9  local: q3,4
    APPLY_GATE_GAUGED(3, 0); APPLY_GATE_GAUGED(3, 3); APPLY_GATE_GAUGED(3, 1);
    APPLY_GATE_GAUGED(3, 4); APPLY_GATE_GAUGED(3, 2); APPLY_GATE_GAUGED(3, 5);
    APPLY_GATE_GAUGED(3, 6); APPLY_GATE_GAUGED(3, 7); APPLY_GATE_GAUGED(3, 8);
    APPLY_GATE_GAUGED(3, 9);

#undef APPLY_GATE
#undef APPLY_GATE_GAUGED

    // ---- Packed signed measurement: 4 sums via f2fma with ±1-pair packs ----
    constexpr unsigned rows0 = meas_row(0), rows1 = meas_row(1);
    constexpr unsigned rows2 = meas_row(2), rows3 = meas_row(3);
    const u64 SPP = pk(1.f, 1.f),  SPM = pk(1.f, -1.f);
    const u64 SMP = pk(-1.f, 1.f), SMM = pk(-1.f, -1.f);
    u64 S0p = 0, S1p = 0, S2p = 0, S3p = 0;
#pragma unroll
    for (int g = 0; g < 16; g++) {
        const u64 P = f2fma(Vr[g], Vr[g], f2mul(Vi[g], Vi[g]));
        // signs constant-fold after unroll (par10 on compile-time masks)
        const int a0 = par10((2 * g) & (rows0 & 31u)), b0 = par10((2 * g + 1) & (rows0 & 31u));
        const int a1 = par10((2 * g) & (rows1 & 31u)), b1 = par10((2 * g + 1) & (rows1 & 31u));
        const int a2 = par10((2 * g) & (rows2 & 31u)), b2 = par10((2 * g + 1) & (rows2 & 31u));
        const int a3 = par10((2 * g) & (rows3 & 31u)), b3 = par10((2 * g + 1) & (rows3 & 31u));
        S0p = f2fma(P, a0 ? (b0 ? SMM : SMP) : (b0 ? SPM : SPP), S0p);
        S1p = f2fma(P, a1 ? (b1 ? SMM : SMP) : (b1 ? SPM : SPP), S1p);
        S2p = f2fma(P, a2 ? (b2 ? SMM : SMP) : (b2 ? SPM : SPP), S2p);
        S3p = f2fma(P, a3 ? (b3 ? SMM : SMP) : (b3 ? SPM : SPP), S3p);
    }
    float ev[NC];
    {
        const unsigned lrow[NC] = {rows0 >> 5, rows1 >> 5, rows2 >> 5, rows3 >> 5};
        u64 Sp[NC] = {S0p, S1p, S2p, S3p};
#pragma unroll
        for (int c = 0; c < NC; c++) {
            float lo, hi;
            upk(Sp[c], lo, hi);
            float S = lo + hi;
            const bool ls = (__popc(lane & (int)lrow[c]) & 1) != 0;
            float v = ls ? -S : S;
            v += __shfl_xor_sync(0xffffffffu, v, 16);
            v += __shfl_xor_sync(0xffffffffu, v, 8);
            v += __shfl_xor_sync(0xffffffffu, v, 4);
            v += __shfl_xor_sync(0xffffffffu, v, 2);
            v += __shfl_xor_sync(0xffffffffu, v, 1);
            ev[c] = v;
        }
    }

    if (lane == 0) {
        float t0 = (ev[0] + bias[0]) * scale[0];
        float t1 = (ev[1] + bias[1]) * scale[1];
        float t2 = (ev[2] + bias[2]) * scale[2];
        float t3 = (ev[3] + bias[3]) * scale[3];
        float m = fmaxf(fmaxf(t0, t1), fmaxf(t2, t3));
        float e0 = __expf(t0 - m), e1 = __expf(t1 - m);
        float e2 = __expf(t2 - m), e3 = __expf(t3 - m);
        float inv = 1.0f / (e0 + e1 + e2 + e3);
        reinterpret_cast<float4*>(out)[b] =
            make_float4(e0 * inv, e1 * inv, e2 * inv, e3 * inv);
    }
}

extern "C" void kernel_launch(void* const* d_in, const int* in_sizes, int n_in,
                              void* d_out, int out_size) {
    const float* x       = (const float*)d_in[0];  // (B, NQ)
    const float* weights = (const float*)d_in[1];  // (NL, NQ, 3)
    const float* bias    = (const float*)d_in[2];  // (C,)
    const float* scale   = (const float*)d_in[3];  // (C,)
    float* out = (float*)d_out;                    // (B, C)

    vqc_kernel<<<BATCH / 8, 256>>>(x, weights, bias, scale, out);
}